// round 12
// baseline (speedup 1.0000x reference)
#include <cuda_runtime.h>
#include <cuda_bf16.h>
#include <cuda_fp16.h>
#include <cstdint>
#include <cstddef>

// Problem constants
#define BATCH   4
#define T_SEQ   2048
#define CDIM    1024
#define NHEADS  16
#define HDIM    64
#define MROWS   (BATCH * T_SEQ)        // 8192
#define N_QKV   (3 * CDIM)             // 3072

// ---------------------------------------------------------------------------
// Scratch (device globals — no runtime allocation allowed)
// ---------------------------------------------------------------------------
__device__ __align__(256) __half g_xh  [(size_t)MROWS * CDIM];
__device__ __align__(256) __half g_qkvh[(size_t)MROWS * N_QKV];
__device__ __align__(256) __half g_yh  [(size_t)MROWS * CDIM];
__device__ __align__(256) __half g_wah [(size_t)N_QKV * CDIM];
__device__ __align__(256) __half g_wph [(size_t)CDIM * CDIM];
__device__ __align__(256) __half g_wpl [(size_t)CDIM * CDIM];

// ---------------------------------------------------------------------------
// Helpers
// ---------------------------------------------------------------------------
__device__ __forceinline__ uint32_t smem_u32(const void* p) {
    uint32_t a;
    asm("{ .reg .u64 t; cvta.to.shared.u64 t, %1; cvt.u32.u64 %0, t; }"
        : "=r"(a) : "l"(p));
    return a;
}
__device__ __forceinline__ void cp_async16(uint32_t saddr, const void* gaddr) {
    asm volatile("cp.async.ca.shared.global [%0], [%1], 16;"
                 :: "r"(saddr), "l"(gaddr));
}
__device__ __forceinline__ void cp_commit() { asm volatile("cp.async.commit_group;"); }
__device__ __forceinline__ void cp_wait1()  { asm volatile("cp.async.wait_group 1;"); }
__device__ __forceinline__ void cp_wait0()  { asm volatile("cp.async.wait_group 0;"); }

__device__ __forceinline__ void ldmatrix_x4(uint32_t* r, uint32_t addr) {
    asm volatile("ldmatrix.sync.aligned.m8n8.x4.shared.b16 {%0,%1,%2,%3}, [%4];"
                 : "=r"(r[0]), "=r"(r[1]), "=r"(r[2]), "=r"(r[3]) : "r"(addr));
}
__device__ __forceinline__ void ldmatrix_x4_trans(uint32_t* r, uint32_t addr) {
    asm volatile("ldmatrix.sync.aligned.m8n8.x4.trans.shared.b16 {%0,%1,%2,%3}, [%4];"
                 : "=r"(r[0]), "=r"(r[1]), "=r"(r[2]), "=r"(r[3]) : "r"(addr));
}
__device__ __forceinline__ void mma_f16(float* d, const uint32_t* a,
                                        const uint32_t* b, const float* c) {
    asm volatile(
        "mma.sync.aligned.m16n8k16.row.col.f32.f16.f16.f32 "
        "{%0,%1,%2,%3}, {%4,%5,%6,%7}, {%8,%9}, {%10,%11,%12,%13};"
        : "=f"(d[0]), "=f"(d[1]), "=f"(d[2]), "=f"(d[3])
        : "r"(a[0]), "r"(a[1]), "r"(a[2]), "r"(a[3]),
          "r"(b[0]), "r"(b[1]),
          "f"(c[0]), "f"(c[1]), "f"(c[2]), "f"(c[3]));
}
__device__ __forceinline__ uint32_t packh2(float x, float y) {
    __half2 p;
    p.x = __float2half_rn(x); p.y = __float2half_rn(y);
    return *(uint32_t*)&p;
}

// ---------------------------------------------------------------------------
// Conversion kernels
// ---------------------------------------------------------------------------
__global__ void __launch_bounds__(256)
xcvt_kernel(const float* __restrict__ in, __half* __restrict__ outH, int n4) {
    int i = blockIdx.x * 256 + threadIdx.x;
    if (i >= n4) return;
    float4 v = ((const float4*)in)[i];
    uint2 o;
    o.x = packh2(v.x, v.y);
    o.y = packh2(v.z, v.w);
    ((uint2*)outH)[i] = o;
}

__global__ void __launch_bounds__(1024)
t16_kernel(const float* __restrict__ w, __half* __restrict__ tHi, int K, int N) {
    __shared__ float tile[32][33];
    int n0 = blockIdx.x * 32, k0 = blockIdx.y * 32;
    int tx = threadIdx.x & 31, ty = threadIdx.x >> 5;
    tile[ty][tx] = w[(size_t)(k0 + ty) * N + n0 + tx];
    __syncthreads();
    tHi[(size_t)(n0 + ty) * K + k0 + tx] = __float2half_rn(tile[tx][ty]);
}

__global__ void __launch_bounds__(1024)
tsplit16_kernel(const float* __restrict__ w, __half* __restrict__ tHi,
                __half* __restrict__ tLo, int K, int N) {
    __shared__ float tile[32][33];
    int n0 = blockIdx.x * 32, k0 = blockIdx.y * 32;
    int tx = threadIdx.x & 31, ty = threadIdx.x >> 5;
    tile[ty][tx] = w[(size_t)(k0 + ty) * N + n0 + tx];
    __syncthreads();
    float v = tile[tx][ty];
    __half h = __float2half_rn(v);
    __half l = __float2half_rn(v - __half2float(h));
    size_t o = (size_t)(n0 + ty) * K + k0 + tx;
    tHi[o] = h;
    tLo[o] = l;
}

// ---------------------------------------------------------------------------
// HMMA fp16 GEMM, CTA 128x256, warp tile 64x64 (8 warps 2x4), BK=32,
// 2-stage cp.async, 1 CTA/SM (~180 regs). Templated on dual-B plane.
// C = Ah[M,K] * (Bh[+Bl])^T[N,K]; out fp32 C or fp16 Ch.
// ---------------------------------------------------------------------------
#define GBK 32
#define ROWB 80
#define APLANE (128 * ROWB)                    // 10240
#define BPLANE (256 * ROWB)                    // 20480
#define GEMM_SMEM_1B (2 * (APLANE + BPLANE))       // 61440
#define GEMM_SMEM_2B (2 * (APLANE + 2 * BPLANE))   // 102400

template <bool DUALB>
__global__ void __launch_bounds__(256, 1)
gemm_f16(const __half* __restrict__ Ah, const __half* __restrict__ Bh,
         const __half* __restrict__ Bl, float* __restrict__ C,
         __half* __restrict__ Ch, int N, int K) {
    constexpr uint32_t STAGE = APLANE + (DUALB ? 2 : 1) * BPLANE;
    extern __shared__ char smem[];
    const uint32_t sb = smem_u32(smem);

    const int tid  = threadIdx.x;
    const int wid  = tid >> 5;
    const int lane = tid & 31;
    const int wm   = wid >> 2;        // 0..1
    const int wn   = wid & 3;         // 0..3
    const int bn = blockIdx.x, bm = blockIdx.y;

    const __half* aH = Ah + (size_t)(bm * 128) * K;
    const __half* bH = Bh + (size_t)(bn * 256) * K;
    const __half* bL = DUALB ? (Bl + (size_t)(bn * 256) * K) : nullptr;

    // copy mapping: unit u -> row=u>>2 (64 rows per iter), chunk=(u&3)*16B
    const uint32_t uRow = (uint32_t)(tid >> 2);       // 0..63
    const uint32_t sA   = uRow * ROWB + (uint32_t)((tid & 3) * 16);
    const int      gC8  = (tid & 3) * 8;

    // ldmatrix lane addressing
    const int aRow = wm * 64 + (lane & 15);
    const uint32_t aKB = (uint32_t)((lane >> 4) * 16);
    const int bRow = wn * 64 + ((lane >> 4) << 3) + (lane & 7);
    const uint32_t bKB = (uint32_t)(((lane >> 3) & 1) * 16);

    float acc[4][8][4];
    #pragma unroll
    for (int i = 0; i < 4; i++)
        #pragma unroll
        for (int j = 0; j < 8; j++)
            #pragma unroll
            for (int q = 0; q < 4; q++) acc[i][j][q] = 0.0f;

    const int nchunks = K / GBK;

    auto loadChunk = [&](int c) {
        const uint32_t st = sb + (uint32_t)(c & 1) * STAGE;
        const int k0 = c * GBK;
        // A: 128 rows, 2 units/thread
        #pragma unroll
        for (int i = 0; i < 2; i++) {
            cp_async16(st + sA + (uint32_t)(i * 64 * ROWB),
                       aH + (size_t)(uRow + i * 64) * K + k0 + gC8);
        }
        // B planes: 256 rows, 4 units/thread each
        #pragma unroll
        for (int i = 0; i < 4; i++) {
            size_t go = (size_t)(uRow + i * 64) * K + k0 + gC8;
            uint32_t so = sA + (uint32_t)(i * 64 * ROWB);
            cp_async16(st + APLANE + so, bH + go);
            if (DUALB) cp_async16(st + APLANE + BPLANE + so, bL + go);
        }
        cp_commit();
    };

    loadChunk(0);

    for (int c = 0; c < nchunks; c++) {
        const uint32_t st = sb + (uint32_t)(c & 1) * STAGE;
        if (c + 1 < nchunks) {
            loadChunk(c + 1);
            cp_wait1();
        } else {
            cp_wait0();
        }
        __syncthreads();

        #pragma unroll
        for (int kt = 0; kt < 2; kt++) {
            const uint32_t kb  = (uint32_t)(kt * 32) + aKB;
            const uint32_t kbB = (uint32_t)(kt * 32) + bKB;
            uint32_t ah[4][4];
            #pragma unroll
            for (int mt = 0; mt < 4; mt++) {
                uint32_t ro = (uint32_t)((aRow + mt * 16) * ROWB);
                ldmatrix_x4(ah[mt], st + ro + kb);
            }
            #pragma unroll
            for (int nt2 = 0; nt2 < 4; nt2++) {
                uint32_t ro = (uint32_t)((bRow + nt2 * 16) * ROWB);
                uint32_t bh4[4], bl4[4];
                ldmatrix_x4(bh4, st + APLANE + ro + kbB);
                if (DUALB) ldmatrix_x4(bl4, st + APLANE + BPLANE + ro + kbB);
                #pragma unroll
                for (int mt = 0; mt < 4; mt++) {
                    #pragma unroll
                    for (int nh = 0; nh < 2; nh++) {
                        float* a4 = acc[mt][nt2 * 2 + nh];
                        mma_f16(a4, ah[mt], &bh4[nh * 2], a4);
                        if (DUALB) mma_f16(a4, ah[mt], &bl4[nh * 2], a4);
                    }
                }
            }
        }
        __syncthreads();
    }

    const int rBase = bm * 128 + wm * 64 + (lane >> 2);
    const int cBase = bn * 256 + wn * 64 + (lane & 3) * 2;
    if (C) {
        #pragma unroll
        for (int mt = 0; mt < 4; mt++) {
            #pragma unroll
            for (int nt = 0; nt < 8; nt++) {
                float* p0 = C + (size_t)(rBase + mt * 16) * N + cBase + nt * 8;
                float* p1 = p0 + (size_t)8 * N;
                float2 v0; v0.x = acc[mt][nt][0]; v0.y = acc[mt][nt][1];
                float2 v1; v1.x = acc[mt][nt][2]; v1.y = acc[mt][nt][3];
                *(float2*)p0 = v0;
                *(float2*)p1 = v1;
            }
        }
    } else {
        #pragma unroll
        for (int mt = 0; mt < 4; mt++) {
            #pragma unroll
            for (int nt = 0; nt < 8; nt++) {
                size_t i0 = (size_t)(rBase + mt * 16) * N + cBase + nt * 8;
                size_t i1 = i0 + (size_t)8 * N;
                *(uint32_t*)(Ch + i0) = packh2(acc[mt][nt][0], acc[mt][nt][1]);
                *(uint32_t*)(Ch + i1) = packh2(acc[mt][nt][2], acc[mt][nt][3]);
            }
        }
    }
}

// ---------------------------------------------------------------------------
// HMMA flash attention (causal), pure fp16 — unchanged from round 11.
// ---------------------------------------------------------------------------
#define FROWB 144
#define FQ_PLANE 18432
#define FKV_PLANE 9216
#define FSTAGE (2 * FKV_PLANE)
#define FLASH_SMEM (FQ_PLANE + 2 * FSTAGE)      // 55296

__global__ void __launch_bounds__(256, 1)
flash_hmma(const __half* __restrict__ qkvh, __half* __restrict__ yh) {
    extern __shared__ char smem[];
    const uint32_t sb = smem_u32(smem);
    const int tid = threadIdx.x, wid = tid >> 5, lane = tid & 31;
    const int qt = blockIdx.x, h = blockIdx.y, b = blockIdx.z;
    const int q0 = qt * 128;
    const size_t rowB = (size_t)b * T_SEQ;
    const int ntiles = 2 * qt + 2;

    const uint32_t QHI = sb, STG0 = sb + FQ_PLANE;

    #pragma unroll
    for (int i = 0; i < 4; i++) {
        int slot = tid + i * 256;
        int row = slot >> 3, ch = slot & 7;
        size_t g = (rowB + q0 + row) * N_QKV + h * HDIM + ch * 8;
        uint32_t so = (uint32_t)(row * FROWB + ch * 16);
        cp_async16(QHI + so, qkvh + g);
    }
    cp_commit();

    auto loadKV = [&](int kt, uint32_t stg) {
        const int k0 = kt * 64;
        #pragma unroll
        for (int i = 0; i < 2; i++) {
            int slot = tid + i * 256;
            int row = slot >> 3, ch = slot & 7;
            size_t g = (rowB + k0 + row) * N_QKV + h * HDIM + ch * 8;
            uint32_t so = (uint32_t)(row * FROWB + ch * 16);
            cp_async16(stg + so,             qkvh + g + CDIM);
            cp_async16(stg + FKV_PLANE + so, qkvh + g + 2 * CDIM);
        }
        cp_commit();
    };
    loadKV(0, STG0);
    loadKV(1, STG0 + FSTAGE);
    cp_wait1();
    __syncthreads();

    uint32_t qh[4][4];
    {
        const uint32_t ro = (uint32_t)((wid * 16 + (lane & 15)) * FROWB)
                          + (uint32_t)((lane >> 4) * 16);
        #pragma unroll
        for (int ks = 0; ks < 4; ks++)
            ldmatrix_x4(qh[ks], QHI + ro + ks * 32);
    }

    float o[8][4];
    #pragma unroll
    for (int nt = 0; nt < 8; nt++)
        #pragma unroll
        for (int j = 0; j < 4; j++) o[nt][j] = 0.0f;
    float m0 = -1e30f, m1 = -1e30f, l0 = 0.0f, l1 = 0.0f;

    const uint32_t kro = (uint32_t)((((lane >> 4) << 3) + (lane & 7)) * FROWB)
                       + (uint32_t)(((lane >> 3) & 1) * 16);
    const uint32_t vro = (uint32_t)((lane & 15) * FROWB)
                       + (uint32_t)(((lane >> 4) << 3) * 2);

    for (int kt = 0; kt < ntiles; kt++) {
        const uint32_t stg = STG0 + (uint32_t)(kt & 1) * FSTAGE;
        const int k0 = kt * 64;

        float s[8][4];
        #pragma unroll
        for (int nt = 0; nt < 8; nt++)
            #pragma unroll
            for (int j = 0; j < 4; j++) s[nt][j] = 0.0f;

        #pragma unroll
        for (int ks = 0; ks < 4; ks++) {
            uint32_t kh[4][4];
            #pragma unroll
            for (int p4 = 0; p4 < 4; p4++) {
                uint32_t off = kro + (uint32_t)(p4 * 16 * FROWB) + (uint32_t)(ks * 32);
                ldmatrix_x4(kh[p4], stg + off);
            }
            #pragma unroll
            for (int nt = 0; nt < 8; nt++) {
                const uint32_t* bh = &kh[nt >> 1][(nt & 1) * 2];
                mma_f16(s[nt], qh[ks], bh, s[nt]);
            }
        }

        #pragma unroll
        for (int nt = 0; nt < 8; nt++)
            #pragma unroll
            for (int j = 0; j < 4; j++) s[nt][j] *= 0.125f;

        if (kt >= ntiles - 2) {
            const int qr = q0 + wid * 16 + (lane >> 2);
            const int kc = k0 + (lane & 3) * 2;
            #pragma unroll
            for (int nt = 0; nt < 8; nt++)
                #pragma unroll
                for (int j = 0; j < 4; j++)
                    if (kc + nt * 8 + (j & 1) > qr + ((j >> 1) << 3))
                        s[nt][j] = -1e30f;
        }

        float mx0 = -1e30f, mx1 = -1e30f;
        #pragma unroll
        for (int nt = 0; nt < 8; nt++) {
            mx0 = fmaxf(mx0, fmaxf(s[nt][0], s[nt][1]));
            mx1 = fmaxf(mx1, fmaxf(s[nt][2], s[nt][3]));
        }
        mx0 = fmaxf(mx0, __shfl_xor_sync(0xFFFFFFFFu, mx0, 1));
        mx0 = fmaxf(mx0, __shfl_xor_sync(0xFFFFFFFFu, mx0, 2));
        mx1 = fmaxf(mx1, __shfl_xor_sync(0xFFFFFFFFu, mx1, 1));
        mx1 = fmaxf(mx1, __shfl_xor_sync(0xFFFFFFFFu, mx1, 2));

        const float mn0 = fmaxf(m0, mx0), mn1 = fmaxf(m1, mx1);
        const float c0 = __expf(m0 - mn0), c1 = __expf(m1 - mn1);
        m0 = mn0; m1 = mn1;

        float sum0 = 0.0f, sum1 = 0.0f;
        #pragma unroll
        for (int nt = 0; nt < 8; nt++) {
            s[nt][0] = __expf(s[nt][0] - m0); sum0 += s[nt][0];
            s[nt][1] = __expf(s[nt][1] - m0); sum0 += s[nt][1];
            s[nt][2] = __expf(s[nt][2] - m1); sum1 += s[nt][2];
            s[nt][3] = __expf(s[nt][3] - m1); sum1 += s[nt][3];
        }
        sum0 += __shfl_xor_sync(0xFFFFFFFFu, sum0, 1);
        sum0 += __shfl_xor_sync(0xFFFFFFFFu, sum0, 2);
        sum1 += __shfl_xor_sync(0xFFFFFFFFu, sum1, 1);
        sum1 += __shfl_xor_sync(0xFFFFFFFFu, sum1, 2);
        l0 = l0 * c0 + sum0;
        l1 = l1 * c1 + sum1;

        #pragma unroll
        for (int nt = 0; nt < 8; nt++) {
            o[nt][0] *= c0; o[nt][1] *= c0;
            o[nt][2] *= c1; o[nt][3] *= c1;
        }

        #pragma unroll
        for (int ks = 0; ks < 4; ks++) {
            uint32_t pah[4];
            pah[0] = packh2(s[2 * ks][0],     s[2 * ks][1]);
            pah[1] = packh2(s[2 * ks][2],     s[2 * ks][3]);
            pah[2] = packh2(s[2 * ks + 1][0], s[2 * ks + 1][1]);
            pah[3] = packh2(s[2 * ks + 1][2], s[2 * ks + 1][3]);

            uint32_t vh[4][4];
            #pragma unroll
            for (int p4 = 0; p4 < 4; p4++) {
                uint32_t off = vro + (uint32_t)(ks * 16 * FROWB) + (uint32_t)(p4 * 32);
                ldmatrix_x4_trans(vh[p4], stg + FKV_PLANE + off);
            }
            #pragma unroll
            for (int nt = 0; nt < 8; nt++) {
                const uint32_t* bh = &vh[nt >> 1][(nt & 1) * 2];
                mma_f16(o[nt], pah, bh, o[nt]);
            }
        }

        __syncthreads();
        if (kt + 2 < ntiles) loadKV(kt + 2, stg);
        if (kt + 1 < ntiles) {
            if (kt + 2 < ntiles) cp_wait1(); else cp_wait0();
            __syncthreads();
        }
    }

    const float inv0 = 1.0f / l0, inv1 = 1.0f / l1;
    const int row0 = q0 + wid * 16 + (lane >> 2);
    #pragma unroll
    for (int nt = 0; nt < 8; nt++) {
        const int col = h * HDIM + nt * 8 + (lane & 3) * 2;
        size_t i0 = (rowB + row0) * CDIM + col;
        size_t i1 = (rowB + row0 + 8) * CDIM + col;
        *(uint32_t*)(yh + i0) = packh2(o[nt][0] * inv0, o[nt][1] * inv0);
        *(uint32_t*)(yh + i1) = packh2(o[nt][2] * inv1, o[nt][3] * inv1);
    }
}

// ---------------------------------------------------------------------------
// Launch
// ---------------------------------------------------------------------------
extern "C" void kernel_launch(void* const* d_in, const int* in_sizes, int n_in,
                              void* d_out, int out_size) {
    (void)in_sizes; (void)n_in; (void)out_size;
    const float* x      = (const float*)d_in[0];
    const float* w_attn = (const float*)d_in[1];
    const float* w_proj = (const float*)d_in[2];
    float* out = (float*)d_out;

    __half *xh, *yh, *qkvh, *wah, *wph, *wpl;
    cudaGetSymbolAddress((void**)&xh,   g_xh);
    cudaGetSymbolAddress((void**)&qkvh, g_qkvh);
    cudaGetSymbolAddress((void**)&yh,   g_yh);
    cudaGetSymbolAddress((void**)&wah,  g_wah);
    cudaGetSymbolAddress((void**)&wph,  g_wph);
    cudaGetSymbolAddress((void**)&wpl,  g_wpl);

    cudaFuncSetAttribute(gemm_f16<false>, cudaFuncAttributeMaxDynamicSharedMemorySize, GEMM_SMEM_1B);
    cudaFuncSetAttribute(gemm_f16<true>,  cudaFuncAttributeMaxDynamicSharedMemorySize, GEMM_SMEM_2B);
    cudaFuncSetAttribute(flash_hmma,      cudaFuncAttributeMaxDynamicSharedMemorySize, FLASH_SMEM);

    {
        int n4 = MROWS * CDIM / 4;
        xcvt_kernel<<<(n4 + 255) / 256, 256>>>(x, xh, n4);
        t16_kernel<<<dim3(N_QKV / 32, CDIM / 32), 1024>>>(w_attn, wah, CDIM, N_QKV);
        tsplit16_kernel<<<dim3(CDIM / 32, CDIM / 32), 1024>>>(w_proj, wph, wpl, CDIM, CDIM);
    }
    // 1) qkv = x @ w_attn   (pure fp16, 128x256 tile) -> fp16 qkv
    gemm_f16<false><<<dim3(N_QKV / 256, MROWS / 128), 256, GEMM_SMEM_1B>>>(
        xh, wah, nullptr, nullptr, qkvh, N_QKV, CDIM);
    // 2) attention (pure fp16) -> fp16 y
    flash_hmma<<<dim3(T_SEQ / 128, NHEADS, BATCH), 256, FLASH_SMEM>>>(qkvh, yh);
    // 3) out = y @ w_proj   (fp16x2 weights hedge, 128x256 tile, fp32 out)
    gemm_f16<true><<<dim3(CDIM / 256, MROWS / 128), 256, GEMM_SMEM_2B>>>(
        yh, wph, wpl, out, nullptr, CDIM, CDIM);
}

// round 13
// speedup vs baseline: 1.1351x; 1.1351x over previous
#include <cuda_runtime.h>
#include <cuda_bf16.h>
#include <cuda_fp16.h>
#include <cstdint>
#include <cstddef>

// Problem constants
#define BATCH   4
#define T_SEQ   2048
#define CDIM    1024
#define NHEADS  16
#define HDIM    64
#define MROWS   (BATCH * T_SEQ)        // 8192
#define N_QKV   (3 * CDIM)             // 3072

// ---------------------------------------------------------------------------
// Scratch (device globals — no runtime allocation allowed)
// ---------------------------------------------------------------------------
__device__ __align__(256) __half g_xh  [(size_t)MROWS * CDIM];
__device__ __align__(256) __half g_qkvh[(size_t)MROWS * N_QKV];
__device__ __align__(256) __half g_yh  [(size_t)MROWS * CDIM];
__device__ __align__(256) __half g_wah [(size_t)N_QKV * CDIM];
__device__ __align__(256) __half g_wph [(size_t)CDIM * CDIM];

// ---------------------------------------------------------------------------
// Helpers
// ---------------------------------------------------------------------------
__device__ __forceinline__ uint32_t smem_u32(const void* p) {
    uint32_t a;
    asm("{ .reg .u64 t; cvta.to.shared.u64 t, %1; cvt.u32.u64 %0, t; }"
        : "=r"(a) : "l"(p));
    return a;
}
__device__ __forceinline__ void cp_async16(uint32_t saddr, const void* gaddr) {
    asm volatile("cp.async.ca.shared.global [%0], [%1], 16;"
                 :: "r"(saddr), "l"(gaddr));
}
__device__ __forceinline__ void cp_commit() { asm volatile("cp.async.commit_group;"); }
__device__ __forceinline__ void cp_wait1()  { asm volatile("cp.async.wait_group 1;"); }
__device__ __forceinline__ void cp_wait0()  { asm volatile("cp.async.wait_group 0;"); }

__device__ __forceinline__ void ldmatrix_x4(uint32_t* r, uint32_t addr) {
    asm volatile("ldmatrix.sync.aligned.m8n8.x4.shared.b16 {%0,%1,%2,%3}, [%4];"
                 : "=r"(r[0]), "=r"(r[1]), "=r"(r[2]), "=r"(r[3]) : "r"(addr));
}
__device__ __forceinline__ void ldmatrix_x4_trans(uint32_t* r, uint32_t addr) {
    asm volatile("ldmatrix.sync.aligned.m8n8.x4.trans.shared.b16 {%0,%1,%2,%3}, [%4];"
                 : "=r"(r[0]), "=r"(r[1]), "=r"(r[2]), "=r"(r[3]) : "r"(addr));
}
__device__ __forceinline__ void mma_f16(float* d, const uint32_t* a,
                                        const uint32_t* b, const float* c) {
    asm volatile(
        "mma.sync.aligned.m16n8k16.row.col.f32.f16.f16.f32 "
        "{%0,%1,%2,%3}, {%4,%5,%6,%7}, {%8,%9}, {%10,%11,%12,%13};"
        : "=f"(d[0]), "=f"(d[1]), "=f"(d[2]), "=f"(d[3])
        : "r"(a[0]), "r"(a[1]), "r"(a[2]), "r"(a[3]),
          "r"(b[0]), "r"(b[1]),
          "f"(c[0]), "f"(c[1]), "f"(c[2]), "f"(c[3]));
}
__device__ __forceinline__ uint32_t packh2(float x, float y) {
    __half2 p;
    p.x = __float2half_rn(x); p.y = __float2half_rn(y);
    return *(uint32_t*)&p;
}

// ---------------------------------------------------------------------------
// Conversion kernels
// ---------------------------------------------------------------------------
__global__ void __launch_bounds__(256)
xcvt_kernel(const float* __restrict__ in, __half* __restrict__ outH, int n4) {
    int i = blockIdx.x * 256 + threadIdx.x;
    if (i >= n4) return;
    float4 v = ((const float4*)in)[i];
    uint2 o;
    o.x = packh2(v.x, v.y);
    o.y = packh2(v.z, v.w);
    ((uint2*)outH)[i] = o;
}

// Transpose: w[K,N] fp32 -> wT [N,K] half
__global__ void __launch_bounds__(1024)
t16_kernel(const float* __restrict__ w, __half* __restrict__ tHi, int K, int N) {
    __shared__ float tile[32][33];
    int n0 = blockIdx.x * 32, k0 = blockIdx.y * 32;
    int tx = threadIdx.x & 31, ty = threadIdx.x >> 5;
    tile[ty][tx] = w[(size_t)(k0 + ty) * N + n0 + tx];
    __syncthreads();
    tHi[(size_t)(n0 + ty) * K + k0 + tx] = __float2half_rn(tile[tx][ty]);
}

// ---------------------------------------------------------------------------
// HMMA fp16 GEMM (round-11 proven geometry): C = Ah[M,K] * Bh^T[N,K]
// CTA 128x128, BK=32, 256 threads, warp tile 64x32, 2-stage, 2 CTAs/SM.
// Output: fp32 C (if C != null) else fp16 Ch.
// ---------------------------------------------------------------------------
#define GBK 32
#define ROWB 80
#define PLANE_B (128 * ROWB)                   // 10240
#define GEMM_STAGE (2 * PLANE_B)               // A + B
#define GEMM_SMEM (2 * GEMM_STAGE)             // 40960

__global__ void __launch_bounds__(256, 2)
gemm_f16(const __half* __restrict__ Ah, const __half* __restrict__ Bh,
         float* __restrict__ C, __half* __restrict__ Ch, int N, int K) {
    extern __shared__ char smem[];
    const uint32_t sb = smem_u32(smem);

    const int tid  = threadIdx.x;
    const int wid  = tid >> 5;
    const int lane = tid & 31;
    const int wm   = wid >> 2;
    const int wn   = wid & 3;
    const int bn = blockIdx.x, bm = blockIdx.y;

    const __half* aH = Ah + (size_t)(bm * 128) * K;
    const __half* bH = Bh + (size_t)(bn * 128) * K;

    const int ldRow0 = tid >> 2;
    const int ldRow1 = ldRow0 + 64;
    const int ldC8   = (tid & 3) * 8;
    const uint32_t sOff0 = (uint32_t)(ldRow0 * ROWB + ldC8 * 2);
    const uint32_t sOff1 = (uint32_t)(ldRow1 * ROWB + ldC8 * 2);

    const int aRow = wm * 64 + (lane & 15);
    const uint32_t aKB = (uint32_t)((lane >> 4) * 16);
    const int bRow = wn * 32 + ((lane >> 4) << 3) + (lane & 7);
    const uint32_t bKB = (uint32_t)(((lane >> 3) & 1) * 16);

    float acc[4][4][4];
    #pragma unroll
    for (int i = 0; i < 4; i++)
        #pragma unroll
        for (int j = 0; j < 4; j++)
            #pragma unroll
            for (int q = 0; q < 4; q++) acc[i][j][q] = 0.0f;

    const int nchunks = K / GBK;

    auto loadChunk = [&](int c) {
        const uint32_t st = sb + (uint32_t)(c & 1) * GEMM_STAGE;
        const int k0 = c * GBK;
        size_t g0 = (size_t)ldRow0 * K + k0 + ldC8;
        size_t g1 = (size_t)ldRow1 * K + k0 + ldC8;
        cp_async16(st + sOff0,           aH + g0);
        cp_async16(st + sOff1,           aH + g1);
        cp_async16(st + PLANE_B + sOff0, bH + g0);
        cp_async16(st + PLANE_B + sOff1, bH + g1);
        cp_commit();
    };

    loadChunk(0);

    for (int c = 0; c < nchunks; c++) {
        const uint32_t st = sb + (uint32_t)(c & 1) * GEMM_STAGE;
        if (c + 1 < nchunks) {
            loadChunk(c + 1);
            cp_wait1();
        } else {
            cp_wait0();
        }
        __syncthreads();

        #pragma unroll
        for (int kt = 0; kt < 2; kt++) {
            const uint32_t kb  = (uint32_t)(kt * 32) + aKB;
            const uint32_t kbB = (uint32_t)(kt * 32) + bKB;
            uint32_t ah[4][4];
            #pragma unroll
            for (int mt = 0; mt < 4; mt++) {
                uint32_t ro = (uint32_t)((aRow + mt * 16) * ROWB);
                ldmatrix_x4(ah[mt], st + ro + kb);
            }
            uint32_t bh[2][4];
            #pragma unroll
            for (int nt2 = 0; nt2 < 2; nt2++) {
                uint32_t ro = (uint32_t)((bRow + nt2 * 16) * ROWB);
                ldmatrix_x4(bh[nt2], st + PLANE_B + ro + kbB);
            }
            #pragma unroll
            for (int mt = 0; mt < 4; mt++) {
                #pragma unroll
                for (int nt = 0; nt < 4; nt++) {
                    const uint32_t* bhp = &bh[nt >> 1][(nt & 1) * 2];
                    mma_f16(acc[mt][nt], ah[mt], bhp, acc[mt][nt]);
                }
            }
        }
        __syncthreads();
    }

    const int rBase = bm * 128 + wm * 64 + (lane >> 2);
    const int cBase = bn * 128 + wn * 32 + (lane & 3) * 2;
    if (C) {
        #pragma unroll
        for (int mt = 0; mt < 4; mt++) {
            #pragma unroll
            for (int nt = 0; nt < 4; nt++) {
                float* p0 = C + (size_t)(rBase + mt * 16) * N + cBase + nt * 8;
                float* p1 = p0 + (size_t)8 * N;
                float2 v0; v0.x = acc[mt][nt][0]; v0.y = acc[mt][nt][1];
                float2 v1; v1.x = acc[mt][nt][2]; v1.y = acc[mt][nt][3];
                *(float2*)p0 = v0;
                *(float2*)p1 = v1;
            }
        }
    } else {
        #pragma unroll
        for (int mt = 0; mt < 4; mt++) {
            #pragma unroll
            for (int nt = 0; nt < 4; nt++) {
                size_t i0 = (size_t)(rBase + mt * 16) * N + cBase + nt * 8;
                size_t i1 = i0 + (size_t)8 * N;
                *(uint32_t*)(Ch + i0) = packh2(acc[mt][nt][0], acc[mt][nt][1]);
                *(uint32_t*)(Ch + i1) = packh2(acc[mt][nt][2], acc[mt][nt][3]);
            }
        }
    }
}

// ---------------------------------------------------------------------------
// HMMA flash attention (causal), pure fp16 — unchanged from round 11.
// ---------------------------------------------------------------------------
#define FROWB 144
#define FQ_PLANE 18432
#define FKV_PLANE 9216
#define FSTAGE (2 * FKV_PLANE)
#define FLASH_SMEM (FQ_PLANE + 2 * FSTAGE)      // 55296

__global__ void __launch_bounds__(256, 1)
flash_hmma(const __half* __restrict__ qkvh, __half* __restrict__ yh) {
    extern __shared__ char smem[];
    const uint32_t sb = smem_u32(smem);
    const int tid = threadIdx.x, wid = tid >> 5, lane = tid & 31;
    const int qt = blockIdx.x, h = blockIdx.y, b = blockIdx.z;
    const int q0 = qt * 128;
    const size_t rowB = (size_t)b * T_SEQ;
    const int ntiles = 2 * qt + 2;

    const uint32_t QHI = sb, STG0 = sb + FQ_PLANE;

    #pragma unroll
    for (int i = 0; i < 4; i++) {
        int slot = tid + i * 256;
        int row = slot >> 3, ch = slot & 7;
        size_t g = (rowB + q0 + row) * N_QKV + h * HDIM + ch * 8;
        uint32_t so = (uint32_t)(row * FROWB + ch * 16);
        cp_async16(QHI + so, qkvh + g);
    }
    cp_commit();

    auto loadKV = [&](int kt, uint32_t stg) {
        const int k0 = kt * 64;
        #pragma unroll
        for (int i = 0; i < 2; i++) {
            int slot = tid + i * 256;
            int row = slot >> 3, ch = slot & 7;
            size_t g = (rowB + k0 + row) * N_QKV + h * HDIM + ch * 8;
            uint32_t so = (uint32_t)(row * FROWB + ch * 16);
            cp_async16(stg + so,             qkvh + g + CDIM);
            cp_async16(stg + FKV_PLANE + so, qkvh + g + 2 * CDIM);
        }
        cp_commit();
    };
    loadKV(0, STG0);
    loadKV(1, STG0 + FSTAGE);
    cp_wait1();
    __syncthreads();

    uint32_t qh[4][4];
    {
        const uint32_t ro = (uint32_t)((wid * 16 + (lane & 15)) * FROWB)
                          + (uint32_t)((lane >> 4) * 16);
        #pragma unroll
        for (int ks = 0; ks < 4; ks++)
            ldmatrix_x4(qh[ks], QHI + ro + ks * 32);
    }

    float o[8][4];
    #pragma unroll
    for (int nt = 0; nt < 8; nt++)
        #pragma unroll
        for (int j = 0; j < 4; j++) o[nt][j] = 0.0f;
    float m0 = -1e30f, m1 = -1e30f, l0 = 0.0f, l1 = 0.0f;

    const uint32_t kro = (uint32_t)((((lane >> 4) << 3) + (lane & 7)) * FROWB)
                       + (uint32_t)(((lane >> 3) & 1) * 16);
    const uint32_t vro = (uint32_t)((lane & 15) * FROWB)
                       + (uint32_t)(((lane >> 4) << 3) * 2);

    for (int kt = 0; kt < ntiles; kt++) {
        const uint32_t stg = STG0 + (uint32_t)(kt & 1) * FSTAGE;
        const int k0 = kt * 64;

        float s[8][4];
        #pragma unroll
        for (int nt = 0; nt < 8; nt++)
            #pragma unroll
            for (int j = 0; j < 4; j++) s[nt][j] = 0.0f;

        #pragma unroll
        for (int ks = 0; ks < 4; ks++) {
            uint32_t kh[4][4];
            #pragma unroll
            for (int p4 = 0; p4 < 4; p4++) {
                uint32_t off = kro + (uint32_t)(p4 * 16 * FROWB) + (uint32_t)(ks * 32);
                ldmatrix_x4(kh[p4], stg + off);
            }
            #pragma unroll
            for (int nt = 0; nt < 8; nt++) {
                const uint32_t* bh = &kh[nt >> 1][(nt & 1) * 2];
                mma_f16(s[nt], qh[ks], bh, s[nt]);
            }
        }

        #pragma unroll
        for (int nt = 0; nt < 8; nt++)
            #pragma unroll
            for (int j = 0; j < 4; j++) s[nt][j] *= 0.125f;

        if (kt >= ntiles - 2) {
            const int qr = q0 + wid * 16 + (lane >> 2);
            const int kc = k0 + (lane & 3) * 2;
            #pragma unroll
            for (int nt = 0; nt < 8; nt++)
                #pragma unroll
                for (int j = 0; j < 4; j++)
                    if (kc + nt * 8 + (j & 1) > qr + ((j >> 1) << 3))
                        s[nt][j] = -1e30f;
        }

        float mx0 = -1e30f, mx1 = -1e30f;
        #pragma unroll
        for (int nt = 0; nt < 8; nt++) {
            mx0 = fmaxf(mx0, fmaxf(s[nt][0], s[nt][1]));
            mx1 = fmaxf(mx1, fmaxf(s[nt][2], s[nt][3]));
        }
        mx0 = fmaxf(mx0, __shfl_xor_sync(0xFFFFFFFFu, mx0, 1));
        mx0 = fmaxf(mx0, __shfl_xor_sync(0xFFFFFFFFu, mx0, 2));
        mx1 = fmaxf(mx1, __shfl_xor_sync(0xFFFFFFFFu, mx1, 1));
        mx1 = fmaxf(mx1, __shfl_xor_sync(0xFFFFFFFFu, mx1, 2));

        const float mn0 = fmaxf(m0, mx0), mn1 = fmaxf(m1, mx1);
        const float c0 = __expf(m0 - mn0), c1 = __expf(m1 - mn1);
        m0 = mn0; m1 = mn1;

        float sum0 = 0.0f, sum1 = 0.0f;
        #pragma unroll
        for (int nt = 0; nt < 8; nt++) {
            s[nt][0] = __expf(s[nt][0] - m0); sum0 += s[nt][0];
            s[nt][1] = __expf(s[nt][1] - m0); sum0 += s[nt][1];
            s[nt][2] = __expf(s[nt][2] - m1); sum1 += s[nt][2];
            s[nt][3] = __expf(s[nt][3] - m1); sum1 += s[nt][3];
        }
        sum0 += __shfl_xor_sync(0xFFFFFFFFu, sum0, 1);
        sum0 += __shfl_xor_sync(0xFFFFFFFFu, sum0, 2);
        sum1 += __shfl_xor_sync(0xFFFFFFFFu, sum1, 1);
        sum1 += __shfl_xor_sync(0xFFFFFFFFu, sum1, 2);
        l0 = l0 * c0 + sum0;
        l1 = l1 * c1 + sum1;

        #pragma unroll
        for (int nt = 0; nt < 8; nt++) {
            o[nt][0] *= c0; o[nt][1] *= c0;
            o[nt][2] *= c1; o[nt][3] *= c1;
        }

        #pragma unroll
        for (int ks = 0; ks < 4; ks++) {
            uint32_t pah[4];
            pah[0] = packh2(s[2 * ks][0],     s[2 * ks][1]);
            pah[1] = packh2(s[2 * ks][2],     s[2 * ks][3]);
            pah[2] = packh2(s[2 * ks + 1][0], s[2 * ks + 1][1]);
            pah[3] = packh2(s[2 * ks + 1][2], s[2 * ks + 1][3]);

            uint32_t vh[4][4];
            #pragma unroll
            for (int p4 = 0; p4 < 4; p4++) {
                uint32_t off = vro + (uint32_t)(ks * 16 * FROWB) + (uint32_t)(p4 * 32);
                ldmatrix_x4_trans(vh[p4], stg + FKV_PLANE + off);
            }
            #pragma unroll
            for (int nt = 0; nt < 8; nt++) {
                const uint32_t* bh = &vh[nt >> 1][(nt & 1) * 2];
                mma_f16(o[nt], pah, bh, o[nt]);
            }
        }

        __syncthreads();
        if (kt + 2 < ntiles) loadKV(kt + 2, stg);
        if (kt + 1 < ntiles) {
            if (kt + 2 < ntiles) cp_wait1(); else cp_wait0();
            __syncthreads();
        }
    }

    const float inv0 = 1.0f / l0, inv1 = 1.0f / l1;
    const int row0 = q0 + wid * 16 + (lane >> 2);
    #pragma unroll
    for (int nt = 0; nt < 8; nt++) {
        const int col = h * HDIM + nt * 8 + (lane & 3) * 2;
        size_t i0 = (rowB + row0) * CDIM + col;
        size_t i1 = (rowB + row0 + 8) * CDIM + col;
        *(uint32_t*)(yh + i0) = packh2(o[nt][0] * inv0, o[nt][1] * inv0);
        *(uint32_t*)(yh + i1) = packh2(o[nt][2] * inv1, o[nt][3] * inv1);
    }
}

// ---------------------------------------------------------------------------
// Launch
// ---------------------------------------------------------------------------
extern "C" void kernel_launch(void* const* d_in, const int* in_sizes, int n_in,
                              void* d_out, int out_size) {
    (void)in_sizes; (void)n_in; (void)out_size;
    const float* x      = (const float*)d_in[0];
    const float* w_attn = (const float*)d_in[1];
    const float* w_proj = (const float*)d_in[2];
    float* out = (float*)d_out;

    __half *xh, *yh, *qkvh, *wah, *wph;
    cudaGetSymbolAddress((void**)&xh,   g_xh);
    cudaGetSymbolAddress((void**)&qkvh, g_qkvh);
    cudaGetSymbolAddress((void**)&yh,   g_yh);
    cudaGetSymbolAddress((void**)&wah,  g_wah);
    cudaGetSymbolAddress((void**)&wph,  g_wph);

    cudaFuncSetAttribute(gemm_f16,  cudaFuncAttributeMaxDynamicSharedMemorySize, GEMM_SMEM);
    cudaFuncSetAttribute(flash_hmma, cudaFuncAttributeMaxDynamicSharedMemorySize, FLASH_SMEM);

    {
        int n4 = MROWS * CDIM / 4;
        xcvt_kernel<<<(n4 + 255) / 256, 256>>>(x, xh, n4);
        t16_kernel<<<dim3(N_QKV / 32, CDIM / 32), 1024>>>(w_attn, wah, CDIM, N_QKV);
        t16_kernel<<<dim3(CDIM / 32, CDIM / 32), 1024>>>(w_proj, wph, CDIM, CDIM);
    }
    // 1) qkv = x @ w_attn   (pure fp16) -> fp16 qkv
    gemm_f16<<<dim3(N_QKV / 128, MROWS / 128), 256, GEMM_SMEM>>>(
        xh, wah, nullptr, qkvh, N_QKV, CDIM);
    // 2) attention (pure fp16) -> fp16 y
    flash_hmma<<<dim3(T_SEQ / 128, NHEADS, BATCH), 256, FLASH_SMEM>>>(qkvh, yh);
    // 3) out = y @ w_proj   (pure fp16, fp32 out)
    gemm_f16<<<dim3(CDIM / 128, MROWS / 128), 256, GEMM_SMEM>>>(
        yh, wph, out, nullptr, CDIM, CDIM);
}

// round 14
// speedup vs baseline: 1.1654x; 1.0267x over previous
#include <cuda_runtime.h>
#include <cuda_bf16.h>
#include <cuda_fp16.h>
#include <cstdint>
#include <cstddef>

// Problem constants
#define BATCH   4
#define T_SEQ   2048
#define CDIM    1024
#define NHEADS  16
#define HDIM    64
#define MROWS   (BATCH * T_SEQ)        // 8192
#define N_QKV   (3 * CDIM)             // 3072

// ---------------------------------------------------------------------------
// Scratch (device globals — no runtime allocation allowed)
// ---------------------------------------------------------------------------
__device__ __align__(256) __half g_xh  [(size_t)MROWS * CDIM];
__device__ __align__(256) __half g_qkvh[(size_t)MROWS * N_QKV];
__device__ __align__(256) __half g_yh  [(size_t)MROWS * CDIM];
__device__ __align__(256) __half g_wah [(size_t)N_QKV * CDIM];
__device__ __align__(256) __half g_wph [(size_t)CDIM * CDIM];

// ---------------------------------------------------------------------------
// Helpers
// ---------------------------------------------------------------------------
__device__ __forceinline__ uint32_t smem_u32(const void* p) {
    uint32_t a;
    asm("{ .reg .u64 t; cvta.to.shared.u64 t, %1; cvt.u32.u64 %0, t; }"
        : "=r"(a) : "l"(p));
    return a;
}
__device__ __forceinline__ void cp_async16(uint32_t saddr, const void* gaddr) {
    asm volatile("cp.async.ca.shared.global [%0], [%1], 16;"
                 :: "r"(saddr), "l"(gaddr));
}
__device__ __forceinline__ void cp_commit() { asm volatile("cp.async.commit_group;"); }
__device__ __forceinline__ void cp_wait1()  { asm volatile("cp.async.wait_group 1;"); }
__device__ __forceinline__ void cp_wait0()  { asm volatile("cp.async.wait_group 0;"); }

__device__ __forceinline__ void ldmatrix_x4(uint32_t* r, uint32_t addr) {
    asm volatile("ldmatrix.sync.aligned.m8n8.x4.shared.b16 {%0,%1,%2,%3}, [%4];"
                 : "=r"(r[0]), "=r"(r[1]), "=r"(r[2]), "=r"(r[3]) : "r"(addr));
}
__device__ __forceinline__ void ldmatrix_x4_trans(uint32_t* r, uint32_t addr) {
    asm volatile("ldmatrix.sync.aligned.m8n8.x4.trans.shared.b16 {%0,%1,%2,%3}, [%4];"
                 : "=r"(r[0]), "=r"(r[1]), "=r"(r[2]), "=r"(r[3]) : "r"(addr));
}
__device__ __forceinline__ void mma_f16(float* d, const uint32_t* a,
                                        const uint32_t* b, const float* c) {
    asm volatile(
        "mma.sync.aligned.m16n8k16.row.col.f32.f16.f16.f32 "
        "{%0,%1,%2,%3}, {%4,%5,%6,%7}, {%8,%9}, {%10,%11,%12,%13};"
        : "=f"(d[0]), "=f"(d[1]), "=f"(d[2]), "=f"(d[3])
        : "r"(a[0]), "r"(a[1]), "r"(a[2]), "r"(a[3]),
          "r"(b[0]), "r"(b[1]),
          "f"(c[0]), "f"(c[1]), "f"(c[2]), "f"(c[3]));
}
__device__ __forceinline__ uint32_t packh2(float x, float y) {
    __half2 p;
    p.x = __float2half_rn(x); p.y = __float2half_rn(y);
    return *(uint32_t*)&p;
}

// ---------------------------------------------------------------------------
// Conversion kernels
// ---------------------------------------------------------------------------
__global__ void __launch_bounds__(256)
xcvt_kernel(const float* __restrict__ in, __half* __restrict__ outH, int n4) {
    int i = blockIdx.x * 256 + threadIdx.x;
    if (i >= n4) return;
    float4 v = ((const float4*)in)[i];
    uint2 o;
    o.x = packh2(v.x, v.y);
    o.y = packh2(v.z, v.w);
    ((uint2*)outH)[i] = o;
}

__global__ void __launch_bounds__(1024)
t16_kernel(const float* __restrict__ w, __half* __restrict__ tHi, int K, int N) {
    __shared__ float tile[32][33];
    int n0 = blockIdx.x * 32, k0 = blockIdx.y * 32;
    int tx = threadIdx.x & 31, ty = threadIdx.x >> 5;
    tile[ty][tx] = w[(size_t)(k0 + ty) * N + n0 + tx];
    __syncthreads();
    tHi[(size_t)(n0 + ty) * K + k0 + tx] = __float2half_rn(tile[tx][ty]);
}

// ---------------------------------------------------------------------------
// HMMA fp16 GEMM (round-13 proven): C = Ah[M,K] * Bh^T[N,K]
// CTA 128x128, BK=32, 256 threads, warp tile 64x32, 2-stage, 2 CTAs/SM.
// ---------------------------------------------------------------------------
#define GBK 32
#define ROWB 80
#define PLANE_B (128 * ROWB)                   // 10240
#define GEMM_STAGE (2 * PLANE_B)
#define GEMM_SMEM (2 * GEMM_STAGE)             // 40960

__global__ void __launch_bounds__(256, 2)
gemm_f16(const __half* __restrict__ Ah, const __half* __restrict__ Bh,
         float* __restrict__ C, __half* __restrict__ Ch, int N, int K) {
    extern __shared__ char smem[];
    const uint32_t sb = smem_u32(smem);

    const int tid  = threadIdx.x;
    const int wid  = tid >> 5;
    const int lane = tid & 31;
    const int wm   = wid >> 2;
    const int wn   = wid & 3;
    const int bn = blockIdx.x, bm = blockIdx.y;

    const __half* aH = Ah + (size_t)(bm * 128) * K;
    const __half* bH = Bh + (size_t)(bn * 128) * K;

    const int ldRow0 = tid >> 2;
    const int ldRow1 = ldRow0 + 64;
    const int ldC8   = (tid & 3) * 8;
    const uint32_t sOff0 = (uint32_t)(ldRow0 * ROWB + ldC8 * 2);
    const uint32_t sOff1 = (uint32_t)(ldRow1 * ROWB + ldC8 * 2);

    const int aRow = wm * 64 + (lane & 15);
    const uint32_t aKB = (uint32_t)((lane >> 4) * 16);
    const int bRow = wn * 32 + ((lane >> 4) << 3) + (lane & 7);
    const uint32_t bKB = (uint32_t)(((lane >> 3) & 1) * 16);

    float acc[4][4][4];
    #pragma unroll
    for (int i = 0; i < 4; i++)
        #pragma unroll
        for (int j = 0; j < 4; j++)
            #pragma unroll
            for (int q = 0; q < 4; q++) acc[i][j][q] = 0.0f;

    const int nchunks = K / GBK;

    auto loadChunk = [&](int c) {
        const uint32_t st = sb + (uint32_t)(c & 1) * GEMM_STAGE;
        const int k0 = c * GBK;
        size_t g0 = (size_t)ldRow0 * K + k0 + ldC8;
        size_t g1 = (size_t)ldRow1 * K + k0 + ldC8;
        cp_async16(st + sOff0,           aH + g0);
        cp_async16(st + sOff1,           aH + g1);
        cp_async16(st + PLANE_B + sOff0, bH + g0);
        cp_async16(st + PLANE_B + sOff1, bH + g1);
        cp_commit();
    };

    loadChunk(0);

    for (int c = 0; c < nchunks; c++) {
        const uint32_t st = sb + (uint32_t)(c & 1) * GEMM_STAGE;
        if (c + 1 < nchunks) {
            loadChunk(c + 1);
            cp_wait1();
        } else {
            cp_wait0();
        }
        __syncthreads();

        #pragma unroll
        for (int kt = 0; kt < 2; kt++) {
            const uint32_t kb  = (uint32_t)(kt * 32) + aKB;
            const uint32_t kbB = (uint32_t)(kt * 32) + bKB;
            uint32_t ah[4][4];
            #pragma unroll
            for (int mt = 0; mt < 4; mt++) {
                uint32_t ro = (uint32_t)((aRow + mt * 16) * ROWB);
                ldmatrix_x4(ah[mt], st + ro + kb);
            }
            uint32_t bh[2][4];
            #pragma unroll
            for (int nt2 = 0; nt2 < 2; nt2++) {
                uint32_t ro = (uint32_t)((bRow + nt2 * 16) * ROWB);
                ldmatrix_x4(bh[nt2], st + PLANE_B + ro + kbB);
            }
            #pragma unroll
            for (int mt = 0; mt < 4; mt++) {
                #pragma unroll
                for (int nt = 0; nt < 4; nt++) {
                    const uint32_t* bhp = &bh[nt >> 1][(nt & 1) * 2];
                    mma_f16(acc[mt][nt], ah[mt], bhp, acc[mt][nt]);
                }
            }
        }
        __syncthreads();
    }

    const int rBase = bm * 128 + wm * 64 + (lane >> 2);
    const int cBase = bn * 128 + wn * 32 + (lane & 3) * 2;
    if (C) {
        #pragma unroll
        for (int mt = 0; mt < 4; mt++) {
            #pragma unroll
            for (int nt = 0; nt < 4; nt++) {
                float* p0 = C + (size_t)(rBase + mt * 16) * N + cBase + nt * 8;
                float* p1 = p0 + (size_t)8 * N;
                float2 v0; v0.x = acc[mt][nt][0]; v0.y = acc[mt][nt][1];
                float2 v1; v1.x = acc[mt][nt][2]; v1.y = acc[mt][nt][3];
                *(float2*)p0 = v0;
                *(float2*)p1 = v1;
            }
        }
    } else {
        #pragma unroll
        for (int mt = 0; mt < 4; mt++) {
            #pragma unroll
            for (int nt = 0; nt < 4; nt++) {
                size_t i0 = (size_t)(rBase + mt * 16) * N + cBase + nt * 8;
                size_t i1 = i0 + (size_t)8 * N;
                *(uint32_t*)(Ch + i0) = packh2(acc[mt][nt][0], acc[mt][nt][1]);
                *(uint32_t*)(Ch + i1) = packh2(acc[mt][nt][2], acc[mt][nt][3]);
            }
        }
    }
}

// ---------------------------------------------------------------------------
// HMMA flash attention (causal), pure fp16, q-tile 256: each warp owns
// 32 q-rows (2 m-tiles), so every K/V fragment feeds 2x the MMAs (halves
// the per-SM LDSM bytes/MMA vs q-tile 128). Per-warp early-out on fully
// masked tiles (warp-uniform; all threads still hit the barriers).
// ---------------------------------------------------------------------------
#define FROWB 144
#define FQ_PLANE (256 * FROWB)                  // 36864
#define FKV_PLANE 9216
#define FSTAGE (2 * FKV_PLANE)                  // 18432
#define FLASH_SMEM (FQ_PLANE + 2 * FSTAGE)      // 73728

__global__ void __launch_bounds__(256, 1)
flash_hmma(const __half* __restrict__ qkvh, __half* __restrict__ yh) {
    extern __shared__ char smem[];
    const uint32_t sb = smem_u32(smem);
    const int tid = threadIdx.x, wid = tid >> 5, lane = tid & 31;
    const int qt = blockIdx.x, h = blockIdx.y, b = blockIdx.z;
    const int q0 = qt * 256;
    const int q0w = q0 + wid * 32;          // this warp's first q row
    const size_t rowB = (size_t)b * T_SEQ;
    const int ntiles = 4 * qt + 4;

    const uint32_t QHI = sb, STG0 = sb + FQ_PLANE;

    // Q loads: 256 rows x 8 chunks = 2048 slots
    #pragma unroll
    for (int i = 0; i < 8; i++) {
        int slot = tid + i * 256;
        int row = slot >> 3, ch = slot & 7;
        size_t g = (rowB + q0 + row) * N_QKV + h * HDIM + ch * 8;
        cp_async16(QHI + (uint32_t)(row * FROWB + ch * 16), qkvh + g);
    }
    cp_commit();

    auto loadKV = [&](int kt, uint32_t stg) {
        const int k0 = kt * 64;
        #pragma unroll
        for (int i = 0; i < 2; i++) {
            int slot = tid + i * 256;
            int row = slot >> 3, ch = slot & 7;
            size_t g = (rowB + k0 + row) * N_QKV + h * HDIM + ch * 8;
            uint32_t so = (uint32_t)(row * FROWB + ch * 16);
            cp_async16(stg + so,             qkvh + g + CDIM);
            cp_async16(stg + FKV_PLANE + so, qkvh + g + 2 * CDIM);
        }
        cp_commit();
    };
    loadKV(0, STG0);
    loadKV(1, STG0 + FSTAGE);
    cp_wait1();
    __syncthreads();

    // Q fragments: 2 m-tiles x 4 k-chunks
    uint32_t qh[2][4][4];
    #pragma unroll
    for (int mt = 0; mt < 2; mt++) {
        const uint32_t ro = (uint32_t)((wid * 32 + mt * 16 + (lane & 15)) * FROWB)
                          + (uint32_t)((lane >> 4) * 16);
        #pragma unroll
        for (int ks = 0; ks < 4; ks++)
            ldmatrix_x4(qh[mt][ks], QHI + ro + ks * 32);
    }

    float o[2][8][4];
    #pragma unroll
    for (int mt = 0; mt < 2; mt++)
        #pragma unroll
        for (int nt = 0; nt < 8; nt++)
            #pragma unroll
            for (int j = 0; j < 4; j++) o[mt][nt][j] = 0.0f;
    float m[2][2], l[2][2];
    #pragma unroll
    for (int mt = 0; mt < 2; mt++) {
        m[mt][0] = -1e30f; m[mt][1] = -1e30f;
        l[mt][0] = 0.0f;   l[mt][1] = 0.0f;
    }

    const uint32_t kro = (uint32_t)((((lane >> 4) << 3) + (lane & 7)) * FROWB)
                       + (uint32_t)(((lane >> 3) & 1) * 16);
    const uint32_t vro = (uint32_t)((lane & 15) * FROWB)
                       + (uint32_t)(((lane >> 4) << 3) * 2);

    for (int kt = 0; kt < ntiles; kt++) {
        const uint32_t stg = STG0 + (uint32_t)(kt & 1) * FSTAGE;
        const int k0 = kt * 64;

        if (k0 <= q0w + 31) {   // warp-uniform: tile not fully masked
            // ---- S = Q K^T
            float s[2][8][4];
            #pragma unroll
            for (int mt = 0; mt < 2; mt++)
                #pragma unroll
                for (int nt = 0; nt < 8; nt++)
                    #pragma unroll
                    for (int j = 0; j < 4; j++) s[mt][nt][j] = 0.0f;

            #pragma unroll
            for (int ks = 0; ks < 4; ks++) {
                uint32_t kh[4][4];
                #pragma unroll
                for (int p4 = 0; p4 < 4; p4++) {
                    uint32_t off = kro + (uint32_t)(p4 * 16 * FROWB) + (uint32_t)(ks * 32);
                    ldmatrix_x4(kh[p4], stg + off);
                }
                #pragma unroll
                for (int mt = 0; mt < 2; mt++)
                    #pragma unroll
                    for (int nt = 0; nt < 8; nt++) {
                        const uint32_t* bh = &kh[nt >> 1][(nt & 1) * 2];
                        mma_f16(s[mt][nt], qh[mt][ks], bh, s[mt][nt]);
                    }
            }

            #pragma unroll
            for (int mt = 0; mt < 2; mt++)
                #pragma unroll
                for (int nt = 0; nt < 8; nt++)
                    #pragma unroll
                    for (int j = 0; j < 4; j++) s[mt][nt][j] *= 0.125f;

            // ---- causal mask (only tiles straddling the diagonal)
            if (k0 + 63 > q0w) {
                const int kc = k0 + (lane & 3) * 2;
                #pragma unroll
                for (int mt = 0; mt < 2; mt++) {
                    const int qr = q0w + mt * 16 + (lane >> 2);
                    #pragma unroll
                    for (int nt = 0; nt < 8; nt++)
                        #pragma unroll
                        for (int j = 0; j < 4; j++)
                            if (kc + nt * 8 + (j & 1) > qr + ((j >> 1) << 3))
                                s[mt][nt][j] = -1e30f;
                }
            }

            // ---- online softmax per m-tile
            #pragma unroll
            for (int mt = 0; mt < 2; mt++) {
                float mx0 = -1e30f, mx1 = -1e30f;
                #pragma unroll
                for (int nt = 0; nt < 8; nt++) {
                    mx0 = fmaxf(mx0, fmaxf(s[mt][nt][0], s[mt][nt][1]));
                    mx1 = fmaxf(mx1, fmaxf(s[mt][nt][2], s[mt][nt][3]));
                }
                mx0 = fmaxf(mx0, __shfl_xor_sync(0xFFFFFFFFu, mx0, 1));
                mx0 = fmaxf(mx0, __shfl_xor_sync(0xFFFFFFFFu, mx0, 2));
                mx1 = fmaxf(mx1, __shfl_xor_sync(0xFFFFFFFFu, mx1, 1));
                mx1 = fmaxf(mx1, __shfl_xor_sync(0xFFFFFFFFu, mx1, 2));

                const float mn0 = fmaxf(m[mt][0], mx0), mn1 = fmaxf(m[mt][1], mx1);
                const float c0 = __expf(m[mt][0] - mn0), c1 = __expf(m[mt][1] - mn1);
                m[mt][0] = mn0; m[mt][1] = mn1;

                float sum0 = 0.0f, sum1 = 0.0f;
                #pragma unroll
                for (int nt = 0; nt < 8; nt++) {
                    s[mt][nt][0] = __expf(s[mt][nt][0] - mn0); sum0 += s[mt][nt][0];
                    s[mt][nt][1] = __expf(s[mt][nt][1] - mn0); sum0 += s[mt][nt][1];
                    s[mt][nt][2] = __expf(s[mt][nt][2] - mn1); sum1 += s[mt][nt][2];
                    s[mt][nt][3] = __expf(s[mt][nt][3] - mn1); sum1 += s[mt][nt][3];
                }
                sum0 += __shfl_xor_sync(0xFFFFFFFFu, sum0, 1);
                sum0 += __shfl_xor_sync(0xFFFFFFFFu, sum0, 2);
                sum1 += __shfl_xor_sync(0xFFFFFFFFu, sum1, 1);
                sum1 += __shfl_xor_sync(0xFFFFFFFFu, sum1, 2);
                l[mt][0] = l[mt][0] * c0 + sum0;
                l[mt][1] = l[mt][1] * c1 + sum1;

                #pragma unroll
                for (int nt = 0; nt < 8; nt++) {
                    o[mt][nt][0] *= c0; o[mt][nt][1] *= c0;
                    o[mt][nt][2] *= c1; o[mt][nt][3] *= c1;
                }
            }

            // ---- O += P V  (V fragments shared across both m-tiles)
            #pragma unroll
            for (int ks = 0; ks < 4; ks++) {
                uint32_t pah[2][4];
                #pragma unroll
                for (int mt = 0; mt < 2; mt++) {
                    pah[mt][0] = packh2(s[mt][2 * ks][0],     s[mt][2 * ks][1]);
                    pah[mt][1] = packh2(s[mt][2 * ks][2],     s[mt][2 * ks][3]);
                    pah[mt][2] = packh2(s[mt][2 * ks + 1][0], s[mt][2 * ks + 1][1]);
                    pah[mt][3] = packh2(s[mt][2 * ks + 1][2], s[mt][2 * ks + 1][3]);
                }
                uint32_t vh[4][4];
                #pragma unroll
                for (int p4 = 0; p4 < 4; p4++) {
                    uint32_t off = vro + (uint32_t)(ks * 16 * FROWB) + (uint32_t)(p4 * 32);
                    ldmatrix_x4_trans(vh[p4], stg + FKV_PLANE + off);
                }
                #pragma unroll
                for (int mt = 0; mt < 2; mt++)
                    #pragma unroll
                    for (int nt = 0; nt < 8; nt++) {
                        const uint32_t* bh = &vh[nt >> 1][(nt & 1) * 2];
                        mma_f16(o[mt][nt], pah[mt], bh, o[mt][nt]);
                    }
            }
        }

        __syncthreads();
        if (kt + 2 < ntiles) loadKV(kt + 2, stg);
        if (kt + 1 < ntiles) {
            if (kt + 2 < ntiles) cp_wait1(); else cp_wait0();
            __syncthreads();
        }
    }

    // ---- epilogue
    #pragma unroll
    for (int mt = 0; mt < 2; mt++) {
        const float inv0 = 1.0f / l[mt][0], inv1 = 1.0f / l[mt][1];
        const int row0 = q0w + mt * 16 + (lane >> 2);
        #pragma unroll
        for (int nt = 0; nt < 8; nt++) {
            const int col = h * HDIM + nt * 8 + (lane & 3) * 2;
            size_t i0 = (rowB + row0) * CDIM + col;
            size_t i1 = (rowB + row0 + 8) * CDIM + col;
            *(uint32_t*)(yh + i0) = packh2(o[mt][nt][0] * inv0, o[mt][nt][1] * inv0);
            *(uint32_t*)(yh + i1) = packh2(o[mt][nt][2] * inv1, o[mt][nt][3] * inv1);
        }
    }
}

// ---------------------------------------------------------------------------
// Launch
// ---------------------------------------------------------------------------
extern "C" void kernel_launch(void* const* d_in, const int* in_sizes, int n_in,
                              void* d_out, int out_size) {
    (void)in_sizes; (void)n_in; (void)out_size;
    const float* x      = (const float*)d_in[0];
    const float* w_attn = (const float*)d_in[1];
    const float* w_proj = (const float*)d_in[2];
    float* out = (float*)d_out;

    __half *xh, *yh, *qkvh, *wah, *wph;
    cudaGetSymbolAddress((void**)&xh,   g_xh);
    cudaGetSymbolAddress((void**)&qkvh, g_qkvh);
    cudaGetSymbolAddress((void**)&yh,   g_yh);
    cudaGetSymbolAddress((void**)&wah,  g_wah);
    cudaGetSymbolAddress((void**)&wph,  g_wph);

    cudaFuncSetAttribute(gemm_f16,   cudaFuncAttributeMaxDynamicSharedMemorySize, GEMM_SMEM);
    cudaFuncSetAttribute(flash_hmma, cudaFuncAttributeMaxDynamicSharedMemorySize, FLASH_SMEM);

    {
        int n4 = MROWS * CDIM / 4;
        xcvt_kernel<<<(n4 + 255) / 256, 256>>>(x, xh, n4);
        t16_kernel<<<dim3(N_QKV / 32, CDIM / 32), 1024>>>(w_attn, wah, CDIM, N_QKV);
        t16_kernel<<<dim3(CDIM / 32, CDIM / 32), 1024>>>(w_proj, wph, CDIM, CDIM);
    }
    // 1) qkv = x @ w_attn   (pure fp16) -> fp16 qkv
    gemm_f16<<<dim3(N_QKV / 128, MROWS / 128), 256, GEMM_SMEM>>>(
        xh, wah, nullptr, qkvh, N_QKV, CDIM);
    // 2) attention (pure fp16, q-tile 256) -> fp16 y
    flash_hmma<<<dim3(T_SEQ / 256, NHEADS, BATCH), 256, FLASH_SMEM>>>(qkvh, yh);
    // 3) out = y @ w_proj   (pure fp16, fp32 out)
    gemm_f16<<<dim3(CDIM / 128, MROWS / 128), 256, GEMM_SMEM>>>(
        yh, wph, out, nullptr, CDIM, CDIM);
}

// round 15
// speedup vs baseline: 1.1800x; 1.0125x over previous
#include <cuda_runtime.h>
#include <cuda_bf16.h>
#include <cuda_fp16.h>
#include <cstdint>
#include <cstddef>

// Problem constants
#define BATCH   4
#define T_SEQ   2048
#define CDIM    1024
#define NHEADS  16
#define HDIM    64
#define MROWS   (BATCH * T_SEQ)        // 8192
#define N_QKV   (3 * CDIM)             // 3072

// ---------------------------------------------------------------------------
// Scratch (device globals — no runtime allocation allowed)
// ---------------------------------------------------------------------------
__device__ __align__(256) __half g_xh  [(size_t)MROWS * CDIM];
__device__ __align__(256) __half g_qkvh[(size_t)MROWS * N_QKV];
__device__ __align__(256) __half g_yh  [(size_t)MROWS * CDIM];
__device__ __align__(256) __half g_wah [(size_t)N_QKV * CDIM];
__device__ __align__(256) __half g_wph [(size_t)CDIM * CDIM];

// ---------------------------------------------------------------------------
// Helpers
// ---------------------------------------------------------------------------
__device__ __forceinline__ uint32_t smem_u32(const void* p) {
    uint32_t a;
    asm("{ .reg .u64 t; cvta.to.shared.u64 t, %1; cvt.u32.u64 %0, t; }"
        : "=r"(a) : "l"(p));
    return a;
}
__device__ __forceinline__ void cp_async16(uint32_t saddr, const void* gaddr) {
    asm volatile("cp.async.ca.shared.global [%0], [%1], 16;"
                 :: "r"(saddr), "l"(gaddr));
}
__device__ __forceinline__ void cp_commit() { asm volatile("cp.async.commit_group;"); }
__device__ __forceinline__ void cp_wait1()  { asm volatile("cp.async.wait_group 1;"); }
__device__ __forceinline__ void cp_wait0()  { asm volatile("cp.async.wait_group 0;"); }

__device__ __forceinline__ void ldmatrix_x4(uint32_t* r, uint32_t addr) {
    asm volatile("ldmatrix.sync.aligned.m8n8.x4.shared.b16 {%0,%1,%2,%3}, [%4];"
                 : "=r"(r[0]), "=r"(r[1]), "=r"(r[2]), "=r"(r[3]) : "r"(addr));
}
__device__ __forceinline__ void ldmatrix_x4_trans(uint32_t* r, uint32_t addr) {
    asm volatile("ldmatrix.sync.aligned.m8n8.x4.trans.shared.b16 {%0,%1,%2,%3}, [%4];"
                 : "=r"(r[0]), "=r"(r[1]), "=r"(r[2]), "=r"(r[3]) : "r"(addr));
}
__device__ __forceinline__ void mma_f16(float* d, const uint32_t* a,
                                        const uint32_t* b, const float* c) {
    asm volatile(
        "mma.sync.aligned.m16n8k16.row.col.f32.f16.f16.f32 "
        "{%0,%1,%2,%3}, {%4,%5,%6,%7}, {%8,%9}, {%10,%11,%12,%13};"
        : "=f"(d[0]), "=f"(d[1]), "=f"(d[2]), "=f"(d[3])
        : "r"(a[0]), "r"(a[1]), "r"(a[2]), "r"(a[3]),
          "r"(b[0]), "r"(b[1]),
          "f"(c[0]), "f"(c[1]), "f"(c[2]), "f"(c[3]));
}
__device__ __forceinline__ uint32_t packh2(float x, float y) {
    __half2 p;
    p.x = __float2half_rn(x); p.y = __float2half_rn(y);
    return *(uint32_t*)&p;
}

// ---------------------------------------------------------------------------
// Conversion kernels
// ---------------------------------------------------------------------------
__global__ void __launch_bounds__(256)
xcvt_kernel(const float* __restrict__ in, __half* __restrict__ outH, int n4) {
    int i = blockIdx.x * 256 + threadIdx.x;
    if (i >= n4) return;
    float4 v = ((const float4*)in)[i];
    uint2 o;
    o.x = packh2(v.x, v.y);
    o.y = packh2(v.z, v.w);
    ((uint2*)outH)[i] = o;
}

__global__ void __launch_bounds__(1024)
t16_kernel(const float* __restrict__ w, __half* __restrict__ tHi, int K, int N) {
    __shared__ float tile[32][33];
    int n0 = blockIdx.x * 32, k0 = blockIdx.y * 32;
    int tx = threadIdx.x & 31, ty = threadIdx.x >> 5;
    tile[ty][tx] = w[(size_t)(k0 + ty) * N + n0 + tx];
    __syncthreads();
    tHi[(size_t)(n0 + ty) * K + k0 + tx] = __float2half_rn(tile[tx][ty]);
}

// ---------------------------------------------------------------------------
// HMMA fp16 GEMM (proven): C = Ah[M,K] * Bh^T[N,K]
// CTA 128x128, BK=32, 256 threads, warp tile 64x32, 2-stage, 2 CTAs/SM.
// ---------------------------------------------------------------------------
#define GBK 32
#define ROWB 80
#define PLANE_B (128 * ROWB)                   // 10240
#define GEMM_STAGE (2 * PLANE_B)
#define GEMM_SMEM (2 * GEMM_STAGE)             // 40960

__global__ void __launch_bounds__(256, 2)
gemm_f16(const __half* __restrict__ Ah, const __half* __restrict__ Bh,
         float* __restrict__ C, __half* __restrict__ Ch, int N, int K) {
    extern __shared__ char smem[];
    const uint32_t sb = smem_u32(smem);

    const int tid  = threadIdx.x;
    const int wid  = tid >> 5;
    const int lane = tid & 31;
    const int wm   = wid >> 2;
    const int wn   = wid & 3;
    const int bn = blockIdx.x, bm = blockIdx.y;

    const __half* aH = Ah + (size_t)(bm * 128) * K;
    const __half* bH = Bh + (size_t)(bn * 128) * K;

    const int ldRow0 = tid >> 2;
    const int ldRow1 = ldRow0 + 64;
    const int ldC8   = (tid & 3) * 8;
    const uint32_t sOff0 = (uint32_t)(ldRow0 * ROWB + ldC8 * 2);
    const uint32_t sOff1 = (uint32_t)(ldRow1 * ROWB + ldC8 * 2);

    const int aRow = wm * 64 + (lane & 15);
    const uint32_t aKB = (uint32_t)((lane >> 4) * 16);
    const int bRow = wn * 32 + ((lane >> 4) << 3) + (lane & 7);
    const uint32_t bKB = (uint32_t)(((lane >> 3) & 1) * 16);

    float acc[4][4][4];
    #pragma unroll
    for (int i = 0; i < 4; i++)
        #pragma unroll
        for (int j = 0; j < 4; j++)
            #pragma unroll
            for (int q = 0; q < 4; q++) acc[i][j][q] = 0.0f;

    const int nchunks = K / GBK;

    auto loadChunk = [&](int c) {
        const uint32_t st = sb + (uint32_t)(c & 1) * GEMM_STAGE;
        const int k0 = c * GBK;
        size_t g0 = (size_t)ldRow0 * K + k0 + ldC8;
        size_t g1 = (size_t)ldRow1 * K + k0 + ldC8;
        cp_async16(st + sOff0,           aH + g0);
        cp_async16(st + sOff1,           aH + g1);
        cp_async16(st + PLANE_B + sOff0, bH + g0);
        cp_async16(st + PLANE_B + sOff1, bH + g1);
        cp_commit();
    };

    loadChunk(0);

    for (int c = 0; c < nchunks; c++) {
        const uint32_t st = sb + (uint32_t)(c & 1) * GEMM_STAGE;
        if (c + 1 < nchunks) {
            loadChunk(c + 1);
            cp_wait1();
        } else {
            cp_wait0();
        }
        __syncthreads();

        #pragma unroll
        for (int kt = 0; kt < 2; kt++) {
            const uint32_t kb  = (uint32_t)(kt * 32) + aKB;
            const uint32_t kbB = (uint32_t)(kt * 32) + bKB;
            uint32_t ah[4][4];
            #pragma unroll
            for (int mt = 0; mt < 4; mt++) {
                uint32_t ro = (uint32_t)((aRow + mt * 16) * ROWB);
                ldmatrix_x4(ah[mt], st + ro + kb);
            }
            uint32_t bh[2][4];
            #pragma unroll
            for (int nt2 = 0; nt2 < 2; nt2++) {
                uint32_t ro = (uint32_t)((bRow + nt2 * 16) * ROWB);
                ldmatrix_x4(bh[nt2], st + PLANE_B + ro + kbB);
            }
            #pragma unroll
            for (int mt = 0; mt < 4; mt++) {
                #pragma unroll
                for (int nt = 0; nt < 4; nt++) {
                    const uint32_t* bhp = &bh[nt >> 1][(nt & 1) * 2];
                    mma_f16(acc[mt][nt], ah[mt], bhp, acc[mt][nt]);
                }
            }
        }
        __syncthreads();
    }

    const int rBase = bm * 128 + wm * 64 + (lane >> 2);
    const int cBase = bn * 128 + wn * 32 + (lane & 3) * 2;
    if (C) {
        #pragma unroll
        for (int mt = 0; mt < 4; mt++) {
            #pragma unroll
            for (int nt = 0; nt < 4; nt++) {
                float* p0 = C + (size_t)(rBase + mt * 16) * N + cBase + nt * 8;
                float* p1 = p0 + (size_t)8 * N;
                float2 v0; v0.x = acc[mt][nt][0]; v0.y = acc[mt][nt][1];
                float2 v1; v1.x = acc[mt][nt][2]; v1.y = acc[mt][nt][3];
                *(float2*)p0 = v0;
                *(float2*)p1 = v1;
            }
        }
    } else {
        #pragma unroll
        for (int mt = 0; mt < 4; mt++) {
            #pragma unroll
            for (int nt = 0; nt < 4; nt++) {
                size_t i0 = (size_t)(rBase + mt * 16) * N + cBase + nt * 8;
                size_t i1 = i0 + (size_t)8 * N;
                *(uint32_t*)(Ch + i0) = packh2(acc[mt][nt][0], acc[mt][nt][1]);
                *(uint32_t*)(Ch + i1) = packh2(acc[mt][nt][2], acc[mt][nt][3]);
            }
        }
    }
}

// ---------------------------------------------------------------------------
// HMMA flash attention (causal), pure fp16, q-tile 128, 2 CTAs/SM.
// Per-CTA ktile: smem port ~640cyc < tensor ~1024cyc, so doubling CTAs/SM
// raises tensor occupancy without hitting the port ceiling.
// ---------------------------------------------------------------------------
#define FROWB 144
#define FQ_PLANE 18432
#define FKV_PLANE 9216
#define FSTAGE (2 * FKV_PLANE)
#define FLASH_SMEM (FQ_PLANE + 2 * FSTAGE)      // 55296; x2 = 110592 <= 228KB

__global__ void __launch_bounds__(256, 2)
flash_hmma(const __half* __restrict__ qkvh, __half* __restrict__ yh) {
    extern __shared__ char smem[];
    const uint32_t sb = smem_u32(smem);
    const int tid = threadIdx.x, wid = tid >> 5, lane = tid & 31;
    const int qt = blockIdx.x, h = blockIdx.y, b = blockIdx.z;
    const int q0 = qt * 128;
    const size_t rowB = (size_t)b * T_SEQ;
    const int ntiles = 2 * qt + 2;

    const uint32_t QHI = sb, STG0 = sb + FQ_PLANE;

    #pragma unroll
    for (int i = 0; i < 4; i++) {
        int slot = tid + i * 256;
        int row = slot >> 3, ch = slot & 7;
        size_t g = (rowB + q0 + row) * N_QKV + h * HDIM + ch * 8;
        cp_async16(QHI + (uint32_t)(row * FROWB + ch * 16), qkvh + g);
    }
    cp_commit();

    auto loadKV = [&](int kt, uint32_t stg) {
        const int k0 = kt * 64;
        #pragma unroll
        for (int i = 0; i < 2; i++) {
            int slot = tid + i * 256;
            int row = slot >> 3, ch = slot & 7;
            size_t g = (rowB + k0 + row) * N_QKV + h * HDIM + ch * 8;
            uint32_t so = (uint32_t)(row * FROWB + ch * 16);
            cp_async16(stg + so,             qkvh + g + CDIM);
            cp_async16(stg + FKV_PLANE + so, qkvh + g + 2 * CDIM);
        }
        cp_commit();
    };
    loadKV(0, STG0);
    loadKV(1, STG0 + FSTAGE);
    cp_wait1();
    __syncthreads();

    uint32_t qh[4][4];
    {
        const uint32_t ro = (uint32_t)((wid * 16 + (lane & 15)) * FROWB)
                          + (uint32_t)((lane >> 4) * 16);
        #pragma unroll
        for (int ks = 0; ks < 4; ks++)
            ldmatrix_x4(qh[ks], QHI + ro + ks * 32);
    }

    float o[8][4];
    #pragma unroll
    for (int nt = 0; nt < 8; nt++)
        #pragma unroll
        for (int j = 0; j < 4; j++) o[nt][j] = 0.0f;
    float m0 = -1e30f, m1 = -1e30f, l0 = 0.0f, l1 = 0.0f;

    const uint32_t kro = (uint32_t)((((lane >> 4) << 3) + (lane & 7)) * FROWB)
                       + (uint32_t)(((lane >> 3) & 1) * 16);
    const uint32_t vro = (uint32_t)((lane & 15) * FROWB)
                       + (uint32_t)(((lane >> 4) << 3) * 2);

    for (int kt = 0; kt < ntiles; kt++) {
        const uint32_t stg = STG0 + (uint32_t)(kt & 1) * FSTAGE;
        const int k0 = kt * 64;

        float s[8][4];
        #pragma unroll
        for (int nt = 0; nt < 8; nt++)
            #pragma unroll
            for (int j = 0; j < 4; j++) s[nt][j] = 0.0f;

        #pragma unroll
        for (int ks = 0; ks < 4; ks++) {
            uint32_t kh[4][4];
            #pragma unroll
            for (int p4 = 0; p4 < 4; p4++) {
                uint32_t off = kro + (uint32_t)(p4 * 16 * FROWB) + (uint32_t)(ks * 32);
                ldmatrix_x4(kh[p4], stg + off);
            }
            #pragma unroll
            for (int nt = 0; nt < 8; nt++) {
                const uint32_t* bh = &kh[nt >> 1][(nt & 1) * 2];
                mma_f16(s[nt], qh[ks], bh, s[nt]);
            }
        }

        #pragma unroll
        for (int nt = 0; nt < 8; nt++)
            #pragma unroll
            for (int j = 0; j < 4; j++) s[nt][j] *= 0.125f;

        if (kt >= ntiles - 2) {
            const int qr = q0 + wid * 16 + (lane >> 2);
            const int kc = k0 + (lane & 3) * 2;
            #pragma unroll
            for (int nt = 0; nt < 8; nt++)
                #pragma unroll
                for (int j = 0; j < 4; j++)
                    if (kc + nt * 8 + (j & 1) > qr + ((j >> 1) << 3))
                        s[nt][j] = -1e30f;
        }

        float mx0 = -1e30f, mx1 = -1e30f;
        #pragma unroll
        for (int nt = 0; nt < 8; nt++) {
            mx0 = fmaxf(mx0, fmaxf(s[nt][0], s[nt][1]));
            mx1 = fmaxf(mx1, fmaxf(s[nt][2], s[nt][3]));
        }
        mx0 = fmaxf(mx0, __shfl_xor_sync(0xFFFFFFFFu, mx0, 1));
        mx0 = fmaxf(mx0, __shfl_xor_sync(0xFFFFFFFFu, mx0, 2));
        mx1 = fmaxf(mx1, __shfl_xor_sync(0xFFFFFFFFu, mx1, 1));
        mx1 = fmaxf(mx1, __shfl_xor_sync(0xFFFFFFFFu, mx1, 2));

        const float mn0 = fmaxf(m0, mx0), mn1 = fmaxf(m1, mx1);
        const float c0 = __expf(m0 - mn0), c1 = __expf(m1 - mn1);
        m0 = mn0; m1 = mn1;

        float sum0 = 0.0f, sum1 = 0.0f;
        #pragma unroll
        for (int nt = 0; nt < 8; nt++) {
            s[nt][0] = __expf(s[nt][0] - m0); sum0 += s[nt][0];
            s[nt][1] = __expf(s[nt][1] - m0); sum0 += s[nt][1];
            s[nt][2] = __expf(s[nt][2] - m1); sum1 += s[nt][2];
            s[nt][3] = __expf(s[nt][3] - m1); sum1 += s[nt][3];
        }
        sum0 += __shfl_xor_sync(0xFFFFFFFFu, sum0, 1);
        sum0 += __shfl_xor_sync(0xFFFFFFFFu, sum0, 2);
        sum1 += __shfl_xor_sync(0xFFFFFFFFu, sum1, 1);
        sum1 += __shfl_xor_sync(0xFFFFFFFFu, sum1, 2);
        l0 = l0 * c0 + sum0;
        l1 = l1 * c1 + sum1;

        #pragma unroll
        for (int nt = 0; nt < 8; nt++) {
            o[nt][0] *= c0; o[nt][1] *= c0;
            o[nt][2] *= c1; o[nt][3] *= c1;
        }

        #pragma unroll
        for (int ks = 0; ks < 4; ks++) {
            uint32_t pah[4];
            pah[0] = packh2(s[2 * ks][0],     s[2 * ks][1]);
            pah[1] = packh2(s[2 * ks][2],     s[2 * ks][3]);
            pah[2] = packh2(s[2 * ks + 1][0], s[2 * ks + 1][1]);
            pah[3] = packh2(s[2 * ks + 1][2], s[2 * ks + 1][3]);

            uint32_t vh[4][4];
            #pragma unroll
            for (int p4 = 0; p4 < 4; p4++) {
                uint32_t off = vro + (uint32_t)(ks * 16 * FROWB) + (uint32_t)(p4 * 32);
                ldmatrix_x4_trans(vh[p4], stg + FKV_PLANE + off);
            }
            #pragma unroll
            for (int nt = 0; nt < 8; nt++) {
                const uint32_t* bh = &vh[nt >> 1][(nt & 1) * 2];
                mma_f16(o[nt], pah, bh, o[nt]);
            }
        }

        __syncthreads();
        if (kt + 2 < ntiles) loadKV(kt + 2, stg);
        if (kt + 1 < ntiles) {
            if (kt + 2 < ntiles) cp_wait1(); else cp_wait0();
            __syncthreads();
        }
    }

    const float inv0 = 1.0f / l0, inv1 = 1.0f / l1;
    const int row0 = q0 + wid * 16 + (lane >> 2);
    #pragma unroll
    for (int nt = 0; nt < 8; nt++) {
        const int col = h * HDIM + nt * 8 + (lane & 3) * 2;
        size_t i0 = (rowB + row0) * CDIM + col;
        size_t i1 = (rowB + row0 + 8) * CDIM + col;
        *(uint32_t*)(yh + i0) = packh2(o[nt][0] * inv0, o[nt][1] * inv0);
        *(uint32_t*)(yh + i1) = packh2(o[nt][2] * inv1, o[nt][3] * inv1);
    }
}

// ---------------------------------------------------------------------------
// Launch
// ---------------------------------------------------------------------------
extern "C" void kernel_launch(void* const* d_in, const int* in_sizes, int n_in,
                              void* d_out, int out_size) {
    (void)in_sizes; (void)n_in; (void)out_size;
    const float* x      = (const float*)d_in[0];
    const float* w_attn = (const float*)d_in[1];
    const float* w_proj = (const float*)d_in[2];
    float* out = (float*)d_out;

    __half *xh, *yh, *qkvh, *wah, *wph;
    cudaGetSymbolAddress((void**)&xh,   g_xh);
    cudaGetSymbolAddress((void**)&qkvh, g_qkvh);
    cudaGetSymbolAddress((void**)&yh,   g_yh);
    cudaGetSymbolAddress((void**)&wah,  g_wah);
    cudaGetSymbolAddress((void**)&wph,  g_wph);

    cudaFuncSetAttribute(gemm_f16,   cudaFuncAttributeMaxDynamicSharedMemorySize, GEMM_SMEM);
    cudaFuncSetAttribute(flash_hmma, cudaFuncAttributeMaxDynamicSharedMemorySize, FLASH_SMEM);

    {
        int n4 = MROWS * CDIM / 4;
        xcvt_kernel<<<(n4 + 255) / 256, 256>>>(x, xh, n4);
        t16_kernel<<<dim3(N_QKV / 32, CDIM / 32), 1024>>>(w_attn, wah, CDIM, N_QKV);
        t16_kernel<<<dim3(CDIM / 32, CDIM / 32), 1024>>>(w_proj, wph, CDIM, CDIM);
    }
    // 1) qkv = x @ w_attn   (pure fp16) -> fp16 qkv
    gemm_f16<<<dim3(N_QKV / 128, MROWS / 128), 256, GEMM_SMEM>>>(
        xh, wah, nullptr, qkvh, N_QKV, CDIM);
    // 2) attention (pure fp16, q-tile 128, 2 CTAs/SM) -> fp16 y
    flash_hmma<<<dim3(T_SEQ / 128, NHEADS, BATCH), 256, FLASH_SMEM>>>(qkvh, yh);
    // 3) out = y @ w_proj   (pure fp16, fp32 out)
    gemm_f16<<<dim3(CDIM / 128, MROWS / 128), 256, GEMM_SMEM>>>(
        yh, wph, out, nullptr, CDIM, CDIM);
}

// round 16
// speedup vs baseline: 1.3554x; 1.1487x over previous
#include <cuda_runtime.h>
#include <cuda_bf16.h>
#include <cuda_fp16.h>
#include <cstdint>
#include <cstddef>

// Problem constants
#define BATCH   4
#define T_SEQ   2048
#define CDIM    1024
#define NHEADS  16
#define HDIM    64
#define MROWS   (BATCH * T_SEQ)        // 8192
#define N_QKV   (3 * CDIM)             // 3072

// ---------------------------------------------------------------------------
// Scratch (device globals — no runtime allocation allowed)
// ---------------------------------------------------------------------------
__device__ __align__(256) __half g_xh  [(size_t)MROWS * CDIM];
__device__ __align__(256) __half g_qkvh[(size_t)MROWS * N_QKV];
__device__ __align__(256) __half g_yh  [(size_t)MROWS * CDIM];
__device__ __align__(256) __half g_wah [(size_t)N_QKV * CDIM];
__device__ __align__(256) __half g_wph [(size_t)CDIM * CDIM];

// ---------------------------------------------------------------------------
// Helpers
// ---------------------------------------------------------------------------
__device__ __forceinline__ uint32_t smem_u32(const void* p) {
    uint32_t a;
    asm("{ .reg .u64 t; cvta.to.shared.u64 t, %1; cvt.u32.u64 %0, t; }"
        : "=r"(a) : "l"(p));
    return a;
}
__device__ __forceinline__ void cp_async16(uint32_t saddr, const void* gaddr) {
    asm volatile("cp.async.ca.shared.global [%0], [%1], 16;"
                 :: "r"(saddr), "l"(gaddr));
}
__device__ __forceinline__ void cp_commit() { asm volatile("cp.async.commit_group;"); }
__device__ __forceinline__ void cp_wait1()  { asm volatile("cp.async.wait_group 1;"); }
__device__ __forceinline__ void cp_wait0()  { asm volatile("cp.async.wait_group 0;"); }

__device__ __forceinline__ void ldmatrix_x4(uint32_t* r, uint32_t addr) {
    asm volatile("ldmatrix.sync.aligned.m8n8.x4.shared.b16 {%0,%1,%2,%3}, [%4];"
                 : "=r"(r[0]), "=r"(r[1]), "=r"(r[2]), "=r"(r[3]) : "r"(addr));
}
__device__ __forceinline__ void ldmatrix_x4_trans(uint32_t* r, uint32_t addr) {
    asm volatile("ldmatrix.sync.aligned.m8n8.x4.trans.shared.b16 {%0,%1,%2,%3}, [%4];"
                 : "=r"(r[0]), "=r"(r[1]), "=r"(r[2]), "=r"(r[3]) : "r"(addr));
}
__device__ __forceinline__ void mma_f16(float* d, const uint32_t* a,
                                        const uint32_t* b, const float* c) {
    asm volatile(
        "mma.sync.aligned.m16n8k16.row.col.f32.f16.f16.f32 "
        "{%0,%1,%2,%3}, {%4,%5,%6,%7}, {%8,%9}, {%10,%11,%12,%13};"
        : "=f"(d[0]), "=f"(d[1]), "=f"(d[2]), "=f"(d[3])
        : "r"(a[0]), "r"(a[1]), "r"(a[2]), "r"(a[3]),
          "r"(b[0]), "r"(b[1]),
          "f"(c[0]), "f"(c[1]), "f"(c[2]), "f"(c[3]));
}
__device__ __forceinline__ uint32_t packh2(float x, float y) {
    __half2 p;
    p.x = __float2half_rn(x); p.y = __float2half_rn(y);
    return *(uint32_t*)&p;
}

// ---------------------------------------------------------------------------
// Conversion kernels
// ---------------------------------------------------------------------------
__global__ void __launch_bounds__(256)
xcvt_kernel(const float* __restrict__ in, __half* __restrict__ outH, int n4) {
    int i = blockIdx.x * 256 + threadIdx.x;
    if (i >= n4) return;
    float4 v = ((const float4*)in)[i];
    uint2 o;
    o.x = packh2(v.x, v.y);
    o.y = packh2(v.z, v.w);
    ((uint2*)outH)[i] = o;
}

__global__ void __launch_bounds__(1024)
t16_kernel(const float* __restrict__ w, __half* __restrict__ tHi, int K, int N) {
    __shared__ float tile[32][33];
    int n0 = blockIdx.x * 32, k0 = blockIdx.y * 32;
    int tx = threadIdx.x & 31, ty = threadIdx.x >> 5;
    tile[ty][tx] = w[(size_t)(k0 + ty) * N + n0 + tx];
    __syncthreads();
    tHi[(size_t)(n0 + ty) * K + k0 + tx] = __float2half_rn(tile[tx][ty]);
}

// ---------------------------------------------------------------------------
// HMMA fp16 GEMM: C = Ah[M,K] * Bh^T[N,K]
// CTA 128x128, BK=64, 256 threads, warp tile 64x32, 2-stage, 2 CTAs/SM.
// ROWB=144 (128B data + 16B pad): row*144 mod 128 = row*16 -> 8 consecutive
// rows hit 8 distinct 16B chunks -> conflict-free LDSM, aligned cp.async.
// ---------------------------------------------------------------------------
#define GBK 64
#define ROWB 144
#define PLANE_B (128 * ROWB)                   // 18432
#define GEMM_STAGE (2 * PLANE_B)               // 36864
#define GEMM_SMEM (2 * GEMM_STAGE)             // 73728; x2 CTAs = 147456

__global__ void __launch_bounds__(256, 2)
gemm_f16(const __half* __restrict__ Ah, const __half* __restrict__ Bh,
         float* __restrict__ C, __half* __restrict__ Ch, int N, int K) {
    extern __shared__ char smem[];
    const uint32_t sb = smem_u32(smem);

    const int tid  = threadIdx.x;
    const int wid  = tid >> 5;
    const int lane = tid & 31;
    const int wm   = wid >> 2;
    const int wn   = wid & 3;
    const int bn = blockIdx.x, bm = blockIdx.y;

    const __half* aH = Ah + (size_t)(bm * 128) * K;
    const __half* bH = Bh + (size_t)(bn * 128) * K;

    // copy mapping: 1024 16B-units per plane; unit u: row=u>>3, ch=u&7
    const uint32_t ldRow = (uint32_t)(tid >> 3);       // 0..31
    const uint32_t ldCh  = (uint32_t)(tid & 7);        // 0..7
    const uint32_t sOffB = ldRow * ROWB + ldCh * 16;
    const int      gOffB = (int)(ldCh * 8);            // halves

    const int aRow = wm * 64 + (lane & 15);
    const uint32_t aKB = (uint32_t)((lane >> 4) * 16);
    const int bRow = wn * 32 + ((lane >> 4) << 3) + (lane & 7);
    const uint32_t bKB = (uint32_t)(((lane >> 3) & 1) * 16);

    float acc[4][4][4];
    #pragma unroll
    for (int i = 0; i < 4; i++)
        #pragma unroll
        for (int j = 0; j < 4; j++)
            #pragma unroll
            for (int q = 0; q < 4; q++) acc[i][j][q] = 0.0f;

    const int nchunks = K / GBK;                       // 16

    auto loadChunk = [&](int c) {
        const uint32_t st = sb + (uint32_t)(c & 1) * GEMM_STAGE;
        const int k0 = c * GBK;
        #pragma unroll
        for (int i = 0; i < 4; i++) {
            uint32_t so = sOffB + (uint32_t)(i * 32 * ROWB);
            size_t   go = (size_t)(ldRow + i * 32) * K + k0 + gOffB;
            cp_async16(st + so,           aH + go);
            cp_async16(st + PLANE_B + so, bH + go);
        }
        cp_commit();
    };

    loadChunk(0);

    for (int c = 0; c < nchunks; c++) {
        const uint32_t st = sb + (uint32_t)(c & 1) * GEMM_STAGE;
        if (c + 1 < nchunks) {
            loadChunk(c + 1);
            cp_wait1();
        } else {
            cp_wait0();
        }
        __syncthreads();

        #pragma unroll
        for (int kt = 0; kt < 4; kt++) {
            const uint32_t kb  = (uint32_t)(kt * 32) + aKB;
            const uint32_t kbB = (uint32_t)(kt * 32) + bKB;
            uint32_t ah[4][4];
            #pragma unroll
            for (int mt = 0; mt < 4; mt++) {
                uint32_t ro = (uint32_t)((aRow + mt * 16) * ROWB);
                ldmatrix_x4(ah[mt], st + ro + kb);
            }
            uint32_t bh[2][4];
            #pragma unroll
            for (int nt2 = 0; nt2 < 2; nt2++) {
                uint32_t ro = (uint32_t)((bRow + nt2 * 16) * ROWB);
                ldmatrix_x4(bh[nt2], st + PLANE_B + ro + kbB);
            }
            #pragma unroll
            for (int mt = 0; mt < 4; mt++) {
                #pragma unroll
                for (int nt = 0; nt < 4; nt++) {
                    const uint32_t* bhp = &bh[nt >> 1][(nt & 1) * 2];
                    mma_f16(acc[mt][nt], ah[mt], bhp, acc[mt][nt]);
                }
            }
        }
        __syncthreads();
    }

    const int rBase = bm * 128 + wm * 64 + (lane >> 2);
    const int cBase = bn * 128 + wn * 32 + (lane & 3) * 2;
    if (C) {
        #pragma unroll
        for (int mt = 0; mt < 4; mt++) {
            #pragma unroll
            for (int nt = 0; nt < 4; nt++) {
                float* p0 = C + (size_t)(rBase + mt * 16) * N + cBase + nt * 8;
                float* p1 = p0 + (size_t)8 * N;
                float2 v0; v0.x = acc[mt][nt][0]; v0.y = acc[mt][nt][1];
                float2 v1; v1.x = acc[mt][nt][2]; v1.y = acc[mt][nt][3];
                *(float2*)p0 = v0;
                *(float2*)p1 = v1;
            }
        }
    } else {
        #pragma unroll
        for (int mt = 0; mt < 4; mt++) {
            #pragma unroll
            for (int nt = 0; nt < 4; nt++) {
                size_t i0 = (size_t)(rBase + mt * 16) * N + cBase + nt * 8;
                size_t i1 = i0 + (size_t)8 * N;
                *(uint32_t*)(Ch + i0) = packh2(acc[mt][nt][0], acc[mt][nt][1]);
                *(uint32_t*)(Ch + i1) = packh2(acc[mt][nt][2], acc[mt][nt][3]);
            }
        }
    }
}

// ---------------------------------------------------------------------------
// HMMA flash attention (causal), pure fp16, q-tile 128, 2 CTAs/SM.
// qt reversed (longest causal blocks launch first -> smaller tail wave).
// ---------------------------------------------------------------------------
#define FROWB 144
#define FQ_PLANE 18432
#define FKV_PLANE 9216
#define FSTAGE (2 * FKV_PLANE)
#define FLASH_SMEM (FQ_PLANE + 2 * FSTAGE)      // 55296; x2 = 110592

__global__ void __launch_bounds__(256, 2)
flash_hmma(const __half* __restrict__ qkvh, __half* __restrict__ yh) {
    extern __shared__ char smem[];
    const uint32_t sb = smem_u32(smem);
    const int tid = threadIdx.x, wid = tid >> 5, lane = tid & 31;
    const int qt = gridDim.x - 1 - blockIdx.x;   // longest blocks first
    const int h = blockIdx.y, b = blockIdx.z;
    const int q0 = qt * 128;
    const size_t rowB = (size_t)b * T_SEQ;
    const int ntiles = 2 * qt + 2;

    const uint32_t QHI = sb, STG0 = sb + FQ_PLANE;

    #pragma unroll
    for (int i = 0; i < 4; i++) {
        int slot = tid + i * 256;
        int row = slot >> 3, ch = slot & 7;
        size_t g = (rowB + q0 + row) * N_QKV + h * HDIM + ch * 8;
        cp_async16(QHI + (uint32_t)(row * FROWB + ch * 16), qkvh + g);
    }
    cp_commit();

    auto loadKV = [&](int kt, uint32_t stg) {
        const int k0 = kt * 64;
        #pragma unroll
        for (int i = 0; i < 2; i++) {
            int slot = tid + i * 256;
            int row = slot >> 3, ch = slot & 7;
            size_t g = (rowB + k0 + row) * N_QKV + h * HDIM + ch * 8;
            uint32_t so = (uint32_t)(row * FROWB + ch * 16);
            cp_async16(stg + so,             qkvh + g + CDIM);
            cp_async16(stg + FKV_PLANE + so, qkvh + g + 2 * CDIM);
        }
        cp_commit();
    };
    loadKV(0, STG0);
    loadKV(1, STG0 + FSTAGE);
    cp_wait1();
    __syncthreads();

    uint32_t qh[4][4];
    {
        const uint32_t ro = (uint32_t)((wid * 16 + (lane & 15)) * FROWB)
                          + (uint32_t)((lane >> 4) * 16);
        #pragma unroll
        for (int ks = 0; ks < 4; ks++)
            ldmatrix_x4(qh[ks], QHI + ro + ks * 32);
    }

    float o[8][4];
    #pragma unroll
    for (int nt = 0; nt < 8; nt++)
        #pragma unroll
        for (int j = 0; j < 4; j++) o[nt][j] = 0.0f;
    float m0 = -1e30f, m1 = -1e30f, l0 = 0.0f, l1 = 0.0f;

    const uint32_t kro = (uint32_t)((((lane >> 4) << 3) + (lane & 7)) * FROWB)
                       + (uint32_t)(((lane >> 3) & 1) * 16);
    const uint32_t vro = (uint32_t)((lane & 15) * FROWB)
                       + (uint32_t)(((lane >> 4) << 3) * 2);

    for (int kt = 0; kt < ntiles; kt++) {
        const uint32_t stg = STG0 + (uint32_t)(kt & 1) * FSTAGE;
        const int k0 = kt * 64;

        float s[8][4];
        #pragma unroll
        for (int nt = 0; nt < 8; nt++)
            #pragma unroll
            for (int j = 0; j < 4; j++) s[nt][j] = 0.0f;

        #pragma unroll
        for (int ks = 0; ks < 4; ks++) {
            uint32_t kh[4][4];
            #pragma unroll
            for (int p4 = 0; p4 < 4; p4++) {
                uint32_t off = kro + (uint32_t)(p4 * 16 * FROWB) + (uint32_t)(ks * 32);
                ldmatrix_x4(kh[p4], stg + off);
            }
            #pragma unroll
            for (int nt = 0; nt < 8; nt++) {
                const uint32_t* bh = &kh[nt >> 1][(nt & 1) * 2];
                mma_f16(s[nt], qh[ks], bh, s[nt]);
            }
        }

        #pragma unroll
        for (int nt = 0; nt < 8; nt++)
            #pragma unroll
            for (int j = 0; j < 4; j++) s[nt][j] *= 0.125f;

        if (kt >= ntiles - 2) {
            const int qr = q0 + wid * 16 + (lane >> 2);
            const int kc = k0 + (lane & 3) * 2;
            #pragma unroll
            for (int nt = 0; nt < 8; nt++)
                #pragma unroll
                for (int j = 0; j < 4; j++)
                    if (kc + nt * 8 + (j & 1) > qr + ((j >> 1) << 3))
                        s[nt][j] = -1e30f;
        }

        float mx0 = -1e30f, mx1 = -1e30f;
        #pragma unroll
        for (int nt = 0; nt < 8; nt++) {
            mx0 = fmaxf(mx0, fmaxf(s[nt][0], s[nt][1]));
            mx1 = fmaxf(mx1, fmaxf(s[nt][2], s[nt][3]));
        }
        mx0 = fmaxf(mx0, __shfl_xor_sync(0xFFFFFFFFu, mx0, 1));
        mx0 = fmaxf(mx0, __shfl_xor_sync(0xFFFFFFFFu, mx0, 2));
        mx1 = fmaxf(mx1, __shfl_xor_sync(0xFFFFFFFFu, mx1, 1));
        mx1 = fmaxf(mx1, __shfl_xor_sync(0xFFFFFFFFu, mx1, 2));

        const float mn0 = fmaxf(m0, mx0), mn1 = fmaxf(m1, mx1);
        const float c0 = __expf(m0 - mn0), c1 = __expf(m1 - mn1);
        m0 = mn0; m1 = mn1;

        float sum0 = 0.0f, sum1 = 0.0f;
        #pragma unroll
        for (int nt = 0; nt < 8; nt++) {
            s[nt][0] = __expf(s[nt][0] - m0); sum0 += s[nt][0];
            s[nt][1] = __expf(s[nt][1] - m0); sum0 += s[nt][1];
            s[nt][2] = __expf(s[nt][2] - m1); sum1 += s[nt][2];
            s[nt][3] = __expf(s[nt][3] - m1); sum1 += s[nt][3];
        }
        sum0 += __shfl_xor_sync(0xFFFFFFFFu, sum0, 1);
        sum0 += __shfl_xor_sync(0xFFFFFFFFu, sum0, 2);
        sum1 += __shfl_xor_sync(0xFFFFFFFFu, sum1, 1);
        sum1 += __shfl_xor_sync(0xFFFFFFFFu, sum1, 2);
        l0 = l0 * c0 + sum0;
        l1 = l1 * c1 + sum1;

        #pragma unroll
        for (int nt = 0; nt < 8; nt++) {
            o[nt][0] *= c0; o[nt][1] *= c0;
            o[nt][2] *= c1; o[nt][3] *= c1;
        }

        #pragma unroll
        for (int ks = 0; ks < 4; ks++) {
            uint32_t pah[4];
            pah[0] = packh2(s[2 * ks][0],     s[2 * ks][1]);
            pah[1] = packh2(s[2 * ks][2],     s[2 * ks][3]);
            pah[2] = packh2(s[2 * ks + 1][0], s[2 * ks + 1][1]);
            pah[3] = packh2(s[2 * ks + 1][2], s[2 * ks + 1][3]);

            uint32_t vh[4][4];
            #pragma unroll
            for (int p4 = 0; p4 < 4; p4++) {
                uint32_t off = vro + (uint32_t)(ks * 16 * FROWB) + (uint32_t)(p4 * 32);
                ldmatrix_x4_trans(vh[p4], stg + FKV_PLANE + off);
            }
            #pragma unroll
            for (int nt = 0; nt < 8; nt++) {
                const uint32_t* bh = &vh[nt >> 1][(nt & 1) * 2];
                mma_f16(o[nt], pah, bh, o[nt]);
            }
        }

        __syncthreads();
        if (kt + 2 < ntiles) loadKV(kt + 2, stg);
        if (kt + 1 < ntiles) {
            if (kt + 2 < ntiles) cp_wait1(); else cp_wait0();
            __syncthreads();
        }
    }

    const float inv0 = 1.0f / l0, inv1 = 1.0f / l1;
    const int row0 = q0 + wid * 16 + (lane >> 2);
    #pragma unroll
    for (int nt = 0; nt < 8; nt++) {
        const int col = h * HDIM + nt * 8 + (lane & 3) * 2;
        size_t i0 = (rowB + row0) * CDIM + col;
        size_t i1 = (rowB + row0 + 8) * CDIM + col;
        *(uint32_t*)(yh + i0) = packh2(o[nt][0] * inv0, o[nt][1] * inv0);
        *(uint32_t*)(yh + i1) = packh2(o[nt][2] * inv1, o[nt][3] * inv1);
    }
}

// ---------------------------------------------------------------------------
// Launch
// ---------------------------------------------------------------------------
extern "C" void kernel_launch(void* const* d_in, const int* in_sizes, int n_in,
                              void* d_out, int out_size) {
    (void)in_sizes; (void)n_in; (void)out_size;
    const float* x      = (const float*)d_in[0];
    const float* w_attn = (const float*)d_in[1];
    const float* w_proj = (const float*)d_in[2];
    float* out = (float*)d_out;

    __half *xh, *yh, *qkvh, *wah, *wph;
    cudaGetSymbolAddress((void**)&xh,   g_xh);
    cudaGetSymbolAddress((void**)&qkvh, g_qkvh);
    cudaGetSymbolAddress((void**)&yh,   g_yh);
    cudaGetSymbolAddress((void**)&wah,  g_wah);
    cudaGetSymbolAddress((void**)&wph,  g_wph);

    cudaFuncSetAttribute(gemm_f16,   cudaFuncAttributeMaxDynamicSharedMemorySize, GEMM_SMEM);
    cudaFuncSetAttribute(flash_hmma, cudaFuncAttributeMaxDynamicSharedMemorySize, FLASH_SMEM);

    {
        int n4 = MROWS * CDIM / 4;
        xcvt_kernel<<<(n4 + 255) / 256, 256>>>(x, xh, n4);
        t16_kernel<<<dim3(N_QKV / 32, CDIM / 32), 1024>>>(w_attn, wah, CDIM, N_QKV);
        t16_kernel<<<dim3(CDIM / 32, CDIM / 32), 1024>>>(w_proj, wph, CDIM, CDIM);
    }
    // 1) qkv = x @ w_attn   (pure fp16, BK=64) -> fp16 qkv
    gemm_f16<<<dim3(N_QKV / 128, MROWS / 128), 256, GEMM_SMEM>>>(
        xh, wah, nullptr, qkvh, N_QKV, CDIM);
    // 2) attention (pure fp16, q-tile 128, 2 CTAs/SM, longest-first) -> fp16 y
    flash_hmma<<<dim3(T_SEQ / 128, NHEADS, BATCH), 256, FLASH_SMEM>>>(qkvh, yh);
    // 3) out = y @ w_proj   (pure fp16, BK=64, fp32 out)
    gemm_f16<<<dim3(CDIM / 128, MROWS / 128), 256, GEMM_SMEM>>>(
        yh, wph, out, nullptr, CDIM, CDIM);
}